// round 1
// baseline (speedup 1.0000x reference)
#include <cuda_runtime.h>
#include <cstdint>
#include <cstddef>

// ---------------------------------------------------------------------------
// MegNetBlock fused implementation (fp32 SIMT baseline)
// N=100000 nodes, E=800000 edges, D=64, H=128
// ---------------------------------------------------------------------------

#define NMAX 100000

// scratch (device globals — no allocations allowed)
__device__ float g_v_pre[NMAX * 64];
__device__ float g_ve[NMAX * 64];
__device__ float g_cnt[NMAX];
__device__ float g_u_pre[64];
__device__ float g_ue[64];
__device__ float g_uv[64];

__device__ __forceinline__ float sp(float x) {
    // numerically stable softplus, matches jax.nn.softplus
    return fmaxf(x, 0.0f) + log1pf(expf(-fabsf(x)));
}

// ---------------------------------------------------------------------------
// zero scratch
// ---------------------------------------------------------------------------
__global__ void zero_kernel(int nNodes) {
    int total = nNodes * 64 + nNodes + 128;
    for (int i = blockIdx.x * blockDim.x + threadIdx.x; i < total;
         i += gridDim.x * blockDim.x) {
        if (i < nNodes * 64) {
            g_ve[i] = 0.0f;
        } else if (i < nNodes * 64 + nNodes) {
            g_cnt[i - nNodes * 64] = 0.0f;
        } else {
            int j = i - nNodes * 64 - nNodes;
            if (j < 64) g_ue[j] = 0.0f;
            else        g_uv[j - 64] = 0.0f;
        }
    }
}

// ---------------------------------------------------------------------------
// pre-node dense: v_pre = softplus(node_feat @ W + b)   [N,64]x[64,64]
// 32 rows per block, 128 threads (col = t&63, half = t>>6 handles 16 rows)
// ---------------------------------------------------------------------------
__global__ __launch_bounds__(128) void pre_node_kernel(
    const float* __restrict__ nf, const float* __restrict__ w,
    const float* __restrict__ b) {
    __shared__ float sxl[32 * 64];
    int tid = threadIdx.x;
    size_t base = (size_t)blockIdx.x * 32;

    for (int i = tid; i < 2048; i += 128) sxl[i] = nf[base * 64 + i];
    __syncthreads();

    int col = tid & 63, hf = tid >> 6;
    float bb = b[col];
    float acc[16];
#pragma unroll
    for (int i = 0; i < 16; i++) acc[i] = bb;

    const float* xr = sxl + hf * 16 * 64;
    for (int k = 0; k < 64; k += 4) {
        float wa = w[k * 64 + col], wb = w[(k + 1) * 64 + col];
        float wc = w[(k + 2) * 64 + col], wd = w[(k + 3) * 64 + col];
#pragma unroll
        for (int i = 0; i < 16; i++) {
            float4 xv = *(const float4*)(xr + i * 64 + k);
            acc[i] = fmaf(xv.x, wa, acc[i]);
            acc[i] = fmaf(xv.y, wb, acc[i]);
            acc[i] = fmaf(xv.z, wc, acc[i]);
            acc[i] = fmaf(xv.w, wd, acc[i]);
        }
    }
#pragma unroll
    for (int i = 0; i < 16; i++)
        g_v_pre[(base + hf * 16 + i) * 64 + col] = sp(acc[i]);
}

// ---------------------------------------------------------------------------
// pre-attr dense: u_pre = softplus(graph_attr @ W + b)   [1,64]x[64,64]
// ---------------------------------------------------------------------------
__global__ void pre_attr_kernel(const float* __restrict__ ga,
                                const float* __restrict__ w,
                                const float* __restrict__ b) {
    __shared__ float sg[64];
    int t = threadIdx.x;  // 64 threads
    sg[t] = ga[t];
    __syncthreads();
    float acc = b[t];
    for (int k = 0; k < 64; k++) acc = fmaf(sg[k], w[k * 64 + t], acc);
    g_u_pre[t] = sp(acc);
}

// ---------------------------------------------------------------------------
// fused edge kernel: 32 edges / block, 128 threads
//   x = [v_pre[src], v_pre[dst], softplus(ef@Wpre+b), u_pre]   (256)
//   h0 = sp(x@W0+b0)   h1 = sp(h0@W1+b1)   e_new = sp(h1@W2+b2)
//   e_out = e_new + edge_feat; atomics: ve[dst]+=e_new, cnt[dst]+=1, ue+=sum
// dyn smem: sx 32*256 | shA 32*128 | shB 32*128 | sef 32*64  = 73728 B
// ---------------------------------------------------------------------------
__global__ __launch_bounds__(128) void edge_kernel(
    const float* __restrict__ ef, const int* __restrict__ src,
    const int* __restrict__ dst, const float* __restrict__ pw,
    const float* __restrict__ pb, const float* __restrict__ w0,
    const float* __restrict__ b0, const float* __restrict__ w1,
    const float* __restrict__ b1, const float* __restrict__ w2,
    const float* __restrict__ b2, float* __restrict__ e_out) {
    extern __shared__ float sm[];
    float* sx  = sm;                 // 32*256
    float* shA = sm + 32 * 256;      // 32*128
    float* shB = shA + 32 * 128;     // 32*128
    float* sef = shB + 32 * 128;     // 32*64
    __shared__ int sidx[64];

    int tid = threadIdx.x;
    size_t base = (size_t)blockIdx.x * 32;

    for (int i = tid; i < 2048; i += 128) sef[i] = ef[base * 64 + i];
    if (tid < 32) {
        sidx[tid] = src[base + tid];
        sidx[32 + tid] = dst[base + tid];
    }
    __syncthreads();

    // gather v_src, v_dst, u into sx
    for (int i = tid; i < 2048; i += 128) {
        int e = i >> 6, c = i & 63;
        sx[e * 256 + c]       = g_v_pre[(size_t)sidx[e] * 64 + c];
        sx[e * 256 + 64 + c]  = g_v_pre[(size_t)sidx[32 + e] * 64 + c];
        sx[e * 256 + 192 + c] = g_u_pre[c];
    }

    // pre-edge layer -> sx[:,128:192]
    {
        int col = tid & 63, hf = tid >> 6;
        float bb = pb[col];
        float acc[16];
#pragma unroll
        for (int i = 0; i < 16; i++) acc[i] = bb;
        const float* xr = sef + hf * 16 * 64;
        for (int k = 0; k < 64; k += 4) {
            float wa = pw[k * 64 + col], wb = pw[(k + 1) * 64 + col];
            float wc = pw[(k + 2) * 64 + col], wd = pw[(k + 3) * 64 + col];
#pragma unroll
            for (int i = 0; i < 16; i++) {
                float4 xv = *(const float4*)(xr + i * 64 + k);
                acc[i] = fmaf(xv.x, wa, acc[i]);
                acc[i] = fmaf(xv.y, wb, acc[i]);
                acc[i] = fmaf(xv.z, wc, acc[i]);
                acc[i] = fmaf(xv.w, wd, acc[i]);
            }
        }
#pragma unroll
        for (int i = 0; i < 16; i++)
            sx[(hf * 16 + i) * 256 + 128 + col] = sp(acc[i]);
    }
    __syncthreads();

    // layer 0: [32,256] @ [256,128]
    {
        int j = tid;
        float bb = b0[j];
        float acc[32];
#pragma unroll
        for (int e = 0; e < 32; e++) acc[e] = bb;
        for (int k = 0; k < 256; k += 4) {
            float wa = w0[k * 128 + j], wb = w0[(k + 1) * 128 + j];
            float wc = w0[(k + 2) * 128 + j], wd = w0[(k + 3) * 128 + j];
#pragma unroll
            for (int e = 0; e < 32; e++) {
                float4 xv = *(const float4*)(sx + e * 256 + k);
                acc[e] = fmaf(xv.x, wa, acc[e]);
                acc[e] = fmaf(xv.y, wb, acc[e]);
                acc[e] = fmaf(xv.z, wc, acc[e]);
                acc[e] = fmaf(xv.w, wd, acc[e]);
            }
        }
#pragma unroll
        for (int e = 0; e < 32; e++) shA[e * 128 + j] = sp(acc[e]);
    }
    __syncthreads();

    // layer 1: [32,128] @ [128,128]
    {
        int j = tid;
        float bb = b1[j];
        float acc[32];
#pragma unroll
        for (int e = 0; e < 32; e++) acc[e] = bb;
        for (int k = 0; k < 128; k += 4) {
            float wa = w1[k * 128 + j], wb = w1[(k + 1) * 128 + j];
            float wc = w1[(k + 2) * 128 + j], wd = w1[(k + 3) * 128 + j];
#pragma unroll
            for (int e = 0; e < 32; e++) {
                float4 xv = *(const float4*)(shA + e * 128 + k);
                acc[e] = fmaf(xv.x, wa, acc[e]);
                acc[e] = fmaf(xv.y, wb, acc[e]);
                acc[e] = fmaf(xv.z, wc, acc[e]);
                acc[e] = fmaf(xv.w, wd, acc[e]);
            }
        }
#pragma unroll
        for (int e = 0; e < 32; e++) shB[e * 128 + j] = sp(acc[e]);
    }
    __syncthreads();

    // layer 2: [32,128] @ [128,64] -> e_new (stored in reused sx[0:2048])
    {
        int col = tid & 63, hf = tid >> 6;
        float bb = b2[col];
        float acc[16];
#pragma unroll
        for (int i = 0; i < 16; i++) acc[i] = bb;
        const float* hr = shB + hf * 16 * 128;
        for (int k = 0; k < 128; k += 4) {
            float wa = w2[k * 64 + col], wb = w2[(k + 1) * 64 + col];
            float wc = w2[(k + 2) * 64 + col], wd = w2[(k + 3) * 64 + col];
#pragma unroll
            for (int i = 0; i < 16; i++) {
                float4 xv = *(const float4*)(hr + i * 128 + k);
                acc[i] = fmaf(xv.x, wa, acc[i]);
                acc[i] = fmaf(xv.y, wb, acc[i]);
                acc[i] = fmaf(xv.z, wc, acc[i]);
                acc[i] = fmaf(xv.w, wd, acc[i]);
            }
        }
#pragma unroll
        for (int i = 0; i < 16; i++)
            sx[(hf * 16 + i) * 64 + col] = sp(acc[i]);
    }
    __syncthreads();

    // outputs: skip-add, segment atomics, edge readout partials
    for (int i = tid; i < 2048; i += 128) {
        int e = i >> 6, c = i & 63;
        float v = sx[i];
        e_out[base * 64 + i] = v + sef[i];
        atomicAdd(&g_ve[(size_t)sidx[32 + e] * 64 + c], v);
    }
    if (tid < 32) atomicAdd(&g_cnt[sidx[32 + tid]], 1.0f);
    if (tid < 64) {
        float s = 0.0f;
#pragma unroll
        for (int e = 0; e < 32; e++) s += sx[e * 64 + tid];
        atomicAdd(&g_ue[tid], s);
    }
}

// ---------------------------------------------------------------------------
// fused node kernel: 32 nodes / block, 128 threads
//   x = [v_pre, ve_sum/max(cnt,1), u_pre]  (192) -> MLP 192->128->128->64
//   v_out = v_new + node_feat; uv += colsum(v_new)
// dyn smem: sx 32*192 | shA 32*128 | shB 32*128 | snf 32*64 = 65536 B
// ---------------------------------------------------------------------------
__global__ __launch_bounds__(128) void node_kernel(
    const float* __restrict__ nf, const float* __restrict__ w0,
    const float* __restrict__ b0, const float* __restrict__ w1,
    const float* __restrict__ b1, const float* __restrict__ w2,
    const float* __restrict__ b2, float* __restrict__ v_out) {
    extern __shared__ float sm[];
    float* sx  = sm;                 // 32*192
    float* shA = sm + 32 * 192;      // 32*128
    float* shB = shA + 32 * 128;     // 32*128
    float* snf = shB + 32 * 128;     // 32*64

    int tid = threadIdx.x;
    size_t base = (size_t)blockIdx.x * 32;

    for (int i = tid; i < 2048; i += 128) {
        int n = i >> 6, c = i & 63;
        size_t gn = base + n;
        snf[i] = nf[base * 64 + i];
        sx[n * 192 + c] = g_v_pre[gn * 64 + c];
        float cn = g_cnt[gn];
        sx[n * 192 + 64 + c] = g_ve[gn * 64 + c] / fmaxf(cn, 1.0f);
        sx[n * 192 + 128 + c] = g_u_pre[c];
    }
    __syncthreads();

    // layer 0: [32,192] @ [192,128]
    {
        int j = tid;
        float bb = b0[j];
        float acc[32];
#pragma unroll
        for (int e = 0; e < 32; e++) acc[e] = bb;
        for (int k = 0; k < 192; k += 4) {
            float wa = w0[k * 128 + j], wb = w0[(k + 1) * 128 + j];
            float wc = w0[(k + 2) * 128 + j], wd = w0[(k + 3) * 128 + j];
#pragma unroll
            for (int e = 0; e < 32; e++) {
                float4 xv = *(const float4*)(sx + e * 192 + k);
                acc[e] = fmaf(xv.x, wa, acc[e]);
                acc[e] = fmaf(xv.y, wb, acc[e]);
                acc[e] = fmaf(xv.z, wc, acc[e]);
                acc[e] = fmaf(xv.w, wd, acc[e]);
            }
        }
#pragma unroll
        for (int e = 0; e < 32; e++) shA[e * 128 + j] = sp(acc[e]);
    }
    __syncthreads();

    // layer 1: [32,128] @ [128,128]
    {
        int j = tid;
        float bb = b1[j];
        float acc[32];
#pragma unroll
        for (int e = 0; e < 32; e++) acc[e] = bb;
        for (int k = 0; k < 128; k += 4) {
            float wa = w1[k * 128 + j], wb = w1[(k + 1) * 128 + j];
            float wc = w1[(k + 2) * 128 + j], wd = w1[(k + 3) * 128 + j];
#pragma unroll
            for (int e = 0; e < 32; e++) {
                float4 xv = *(const float4*)(shA + e * 128 + k);
                acc[e] = fmaf(xv.x, wa, acc[e]);
                acc[e] = fmaf(xv.y, wb, acc[e]);
                acc[e] = fmaf(xv.z, wc, acc[e]);
                acc[e] = fmaf(xv.w, wd, acc[e]);
            }
        }
#pragma unroll
        for (int e = 0; e < 32; e++) shB[e * 128 + j] = sp(acc[e]);
    }
    __syncthreads();

    // layer 2: [32,128] @ [128,64] -> v_new in reused sx[0:2048]
    {
        int col = tid & 63, hf = tid >> 6;
        float bb = b2[col];
        float acc[16];
#pragma unroll
        for (int i = 0; i < 16; i++) acc[i] = bb;
        const float* hr = shB + hf * 16 * 128;
        for (int k = 0; k < 128; k += 4) {
            float wa = w2[k * 64 + col], wb = w2[(k + 1) * 64 + col];
            float wc = w2[(k + 2) * 64 + col], wd = w2[(k + 3) * 64 + col];
#pragma unroll
            for (int i = 0; i < 16; i++) {
                float4 xv = *(const float4*)(hr + i * 128 + k);
                acc[i] = fmaf(xv.x, wa, acc[i]);
                acc[i] = fmaf(xv.y, wb, acc[i]);
                acc[i] = fmaf(xv.z, wc, acc[i]);
                acc[i] = fmaf(xv.w, wd, acc[i]);
            }
        }
#pragma unroll
        for (int i = 0; i < 16; i++)
            sx[(hf * 16 + i) * 64 + col] = sp(acc[i]);
    }
    __syncthreads();

    for (int i = tid; i < 2048; i += 128)
        v_out[base * 64 + i] = sx[i] + snf[i];
    if (tid < 64) {
        float s = 0.0f;
#pragma unroll
        for (int e = 0; e < 32; e++) s += sx[e * 64 + tid];
        atomicAdd(&g_uv[tid], s);
    }
}

// ---------------------------------------------------------------------------
// attr kernel: single block, 128 threads
// ---------------------------------------------------------------------------
__global__ void attr_kernel(const float* __restrict__ ga,
                            const float* __restrict__ w0,
                            const float* __restrict__ b0,
                            const float* __restrict__ w1,
                            const float* __restrict__ b1,
                            const float* __restrict__ w2,
                            const float* __restrict__ b2,
                            float* __restrict__ out, float invE, float invN) {
    __shared__ float x[192], h0[128], h1[128];
    int t = threadIdx.x;
    if (t < 64) {
        x[t]       = g_u_pre[t];
        x[64 + t]  = g_ue[t] * invE;
        x[128 + t] = g_uv[t] * invN;
    }
    __syncthreads();
    float acc = b0[t];
    for (int k = 0; k < 192; k++) acc = fmaf(x[k], w0[k * 128 + t], acc);
    h0[t] = sp(acc);
    __syncthreads();
    acc = b1[t];
    for (int k = 0; k < 128; k++) acc = fmaf(h0[k], w1[k * 128 + t], acc);
    h1[t] = sp(acc);
    __syncthreads();
    if (t < 64) {
        float a = b2[t];
        for (int k = 0; k < 128; k++) a = fmaf(h1[k], w2[k * 64 + t], a);
        out[t] = sp(a) + ga[t];
    }
}

// ---------------------------------------------------------------------------
// launch
// ---------------------------------------------------------------------------
extern "C" void kernel_launch(void* const* d_in, const int* in_sizes, int n_in,
                              void* d_out, int out_size) {
    const float* edge_feat  = (const float*)d_in[0];
    const float* node_feat  = (const float*)d_in[1];
    const float* graph_attr = (const float*)d_in[2];
    const int*   src        = (const int*)d_in[3];
    const int*   dst        = (const int*)d_in[4];
    const float* pre_edge_w = (const float*)d_in[5];
    const float* pre_edge_b = (const float*)d_in[6];
    const float* pre_node_w = (const float*)d_in[7];
    const float* pre_node_b = (const float*)d_in[8];
    const float* pre_attr_w = (const float*)d_in[9];
    const float* pre_attr_b = (const float*)d_in[10];
    const float* edge_w0 = (const float*)d_in[11];
    const float* edge_b0 = (const float*)d_in[12];
    const float* edge_w1 = (const float*)d_in[13];
    const float* edge_b1 = (const float*)d_in[14];
    const float* edge_w2 = (const float*)d_in[15];
    const float* edge_b2 = (const float*)d_in[16];
    const float* node_w0 = (const float*)d_in[17];
    const float* node_b0 = (const float*)d_in[18];
    const float* node_w1 = (const float*)d_in[19];
    const float* node_b1 = (const float*)d_in[20];
    const float* node_w2 = (const float*)d_in[21];
    const float* node_b2 = (const float*)d_in[22];
    const float* attr_w0 = (const float*)d_in[23];
    const float* attr_b0 = (const float*)d_in[24];
    const float* attr_w1 = (const float*)d_in[25];
    const float* attr_b1 = (const float*)d_in[26];
    const float* attr_w2 = (const float*)d_in[27];
    const float* attr_b2 = (const float*)d_in[28];

    float* out = (float*)d_out;
    int E = in_sizes[3];        // src element count
    int N = in_sizes[1] / 64;   // node_feat elements / D

    cudaFuncSetAttribute(edge_kernel, cudaFuncAttributeMaxDynamicSharedMemorySize,
                         73728);
    cudaFuncSetAttribute(node_kernel, cudaFuncAttributeMaxDynamicSharedMemorySize,
                         65536);

    zero_kernel<<<256, 256>>>(N);
    pre_node_kernel<<<N / 32, 128>>>(node_feat, pre_node_w, pre_node_b);
    pre_attr_kernel<<<1, 64>>>(graph_attr, pre_attr_w, pre_attr_b);
    edge_kernel<<<E / 32, 128, 73728>>>(edge_feat, src, dst, pre_edge_w,
                                        pre_edge_b, edge_w0, edge_b0, edge_w1,
                                        edge_b1, edge_w2, edge_b2, out);
    node_kernel<<<N / 32, 128, 65536>>>(node_feat, node_w0, node_b0, node_w1,
                                        node_b1, node_w2, node_b2,
                                        out + (size_t)E * 64);
    attr_kernel<<<1, 128>>>(graph_attr, attr_w0, attr_b0, attr_w1, attr_b1,
                            attr_w2, attr_b2,
                            out + (size_t)E * 64 + (size_t)N * 64,
                            1.0f / (float)E, 1.0f / (float)N);
}

// round 3
// speedup vs baseline: 1.3535x; 1.3535x over previous
#include <cuda_runtime.h>
#include <cstdint>
#include <cstddef>

// ---------------------------------------------------------------------------
// MegNetBlock — fp32 with packed f32x2 FFMA + per-node precompute
// N=100000, E=800000, D=64, H=128
// ---------------------------------------------------------------------------

#define NMAX 100000
typedef unsigned long long u64;

// scratch (device globals)
__device__ float  g_v_pre[NMAX * 64];
__device__ float4 g_As[NMAX * 32];       // v_pre @ W0[0:64]    [N,128]
__device__ float4 g_Ad[NMAX * 32];       // v_pre @ W0[64:128]  [N,128]
__device__ float  g_ve[NMAX * 64];
__device__ float  g_cnt[NMAX];
__device__ float  g_u_pre[64];
__device__ __align__(16) float g_ce[128]; // edge L0 const: b0 + u@W0[192:256]
__device__ float  g_cn[128];              // node L0 const: b0 + u@W0n[128:192]
__device__ float  g_ue[64];
__device__ float  g_uv[64];

__device__ __forceinline__ float sp(float x) {
    return fmaxf(x, 0.0f) + log1pf(expf(-fabsf(x)));
}
__device__ __forceinline__ u64 pack2(float a, float b) {
    u64 r; asm("mov.b64 %0,{%1,%2};" : "=l"(r) : "f"(a), "f"(b)); return r;
}
__device__ __forceinline__ void unpack2(u64 v, float& a, float& b) {
    asm("mov.b64 {%0,%1},%2;" : "=f"(a), "=f"(b) : "l"(v));
}
__device__ __forceinline__ void fma2(u64& d, u64 a, u64 b) {
    asm("fma.rn.f32x2 %0,%1,%2,%0;" : "+l"(d) : "l"(a), "l"(b));
}

// ---------------------------------------------------------------------------
__global__ void zero_kernel(int nNodes) {
    int total = nNodes * 64 + nNodes + 128;
    for (int i = blockIdx.x * blockDim.x + threadIdx.x; i < total;
         i += gridDim.x * blockDim.x) {
        if (i < nNodes * 64) g_ve[i] = 0.0f;
        else if (i < nNodes * 64 + nNodes) g_cnt[i - nNodes * 64] = 0.0f;
        else {
            int j = i - nNodes * 64 - nNodes;
            if (j < 64) g_ue[j] = 0.0f; else g_uv[j - 64] = 0.0f;
        }
    }
}

// ---------------------------------------------------------------------------
// pre-attr: u_pre = sp(ga @ W + b)
// ---------------------------------------------------------------------------
__global__ void pre_attr_kernel(const float* __restrict__ ga,
                                const float* __restrict__ w,
                                const float* __restrict__ b) {
    __shared__ float sg[64];
    int t = threadIdx.x;
    sg[t] = ga[t];
    __syncthreads();
    float acc = b[t];
    for (int k = 0; k < 64; k++) acc = fmaf(sg[k], w[k * 64 + t], acc);
    g_u_pre[t] = sp(acc);
}

// ---------------------------------------------------------------------------
// constants: ce = eb0 + u@edge_w0[192:256], cn = nb0 + u@node_w0[128:192]
// ---------------------------------------------------------------------------
__global__ void const_kernel(const float* __restrict__ ew0,
                             const float* __restrict__ eb0,
                             const float* __restrict__ nw0,
                             const float* __restrict__ nb0) {
    __shared__ float su[64];
    int t = threadIdx.x;  // 128
    if (t < 64) su[t] = g_u_pre[t];
    __syncthreads();
    float a = eb0[t], c = nb0[t];
    for (int k = 0; k < 64; k++) {
        a = fmaf(su[k], ew0[(192 + k) * 128 + t], a);
        c = fmaf(su[k], nw0[(128 + k) * 128 + t], c);
    }
    g_ce[t] = a;
    g_cn[t] = c;
}

// ---------------------------------------------------------------------------
// pre-node + per-node precompute: v_pre = sp(nf@Wp+bp); As = v_pre@W0s;
// Ad = v_pre@W0d.  32 nodes / block, 128 threads.
// ---------------------------------------------------------------------------
__global__ __launch_bounds__(128) void pre_nodeA_kernel(
    const float* __restrict__ nf, const float* __restrict__ pw,
    const float* __restrict__ pb, const float* __restrict__ ew0) {
    __shared__ float snf[2048];
    __shared__ float sv[2048];
    int tid = threadIdx.x;
    size_t base = (size_t)blockIdx.x * 32;

    for (int i = tid; i < 512; i += 128)
        ((float4*)snf)[i] = ((const float4*)(nf + base * 64))[i];
    __syncthreads();

    {
        int col = tid & 63, hf = tid >> 6;
        float bb = pb[col];
        float acc[16];
#pragma unroll
        for (int i = 0; i < 16; i++) acc[i] = bb;
        const float* xr = snf + hf * 16 * 64;
        for (int k = 0; k < 64; k += 4) {
            float wa = __ldg(pw + k * 64 + col), wb = __ldg(pw + (k + 1) * 64 + col);
            float wc = __ldg(pw + (k + 2) * 64 + col), wd = __ldg(pw + (k + 3) * 64 + col);
#pragma unroll
            for (int i = 0; i < 16; i++) {
                float4 xv = *(const float4*)(xr + i * 64 + k);
                acc[i] = fmaf(xv.x, wa, acc[i]);
                acc[i] = fmaf(xv.y, wb, acc[i]);
                acc[i] = fmaf(xv.z, wc, acc[i]);
                acc[i] = fmaf(xv.w, wd, acc[i]);
            }
        }
#pragma unroll
        for (int i = 0; i < 16; i++) {
            float v = sp(acc[i]);
            sv[(hf * 16 + i) * 64 + col] = v;
            g_v_pre[(base + hf * 16 + i) * 64 + col] = v;
        }
    }
    __syncthreads();

    // As / Ad: [32,64] @ [64,128]
    float* Asf = (float*)g_As;
    float* Adf = (float*)g_Ad;
    int j = tid;
#pragma unroll 1
    for (int m = 0; m < 2; m++) {
        const float* w = ew0 + (size_t)m * 64 * 128;
        float acc[32];
#pragma unroll
        for (int e = 0; e < 32; e++) acc[e] = 0.0f;
        for (int k = 0; k < 64; k += 4) {
            float wa = __ldg(w + k * 128 + j), wb = __ldg(w + (k + 1) * 128 + j);
            float wc = __ldg(w + (k + 2) * 128 + j), wd = __ldg(w + (k + 3) * 128 + j);
#pragma unroll
            for (int e = 0; e < 32; e++) {
                float4 xv = *(const float4*)(sv + e * 64 + k);
                acc[e] = fmaf(xv.x, wa, acc[e]);
                acc[e] = fmaf(xv.y, wb, acc[e]);
                acc[e] = fmaf(xv.z, wc, acc[e]);
                acc[e] = fmaf(xv.w, wd, acc[e]);
            }
        }
        float* dstp = m ? Adf : Asf;
#pragma unroll
        for (int e = 0; e < 32; e++) dstp[(base + e) * 128 + j] = acc[e];
    }
}

// ---------------------------------------------------------------------------
// fused edge kernel: 32 edges / block, 128 threads, f32x2 packed math.
// smem: sxt 64x36 | g 32x128 | h0t 128x36 | h1t 128x36 | sef 32x64
// ---------------------------------------------------------------------------
__global__ __launch_bounds__(128) void edge_kernel(
    const float* __restrict__ ef, const int* __restrict__ src,
    const int* __restrict__ dst, const float* __restrict__ pw,
    const float* __restrict__ pb, const float* __restrict__ w0,
    const float* __restrict__ b1, const float* __restrict__ w1,
    const float* __restrict__ w2, const float* __restrict__ b2,
    float* __restrict__ e_out) {
    extern __shared__ float sm[];
    float* sxt = sm;                  // 64*36  = 2304
    float* g   = sm + 2304;           // 4096
    float* h0t = sm + 2304 + 4096;    // 128*36 = 4608
    float* h1t = h0t + 4608;          // 4608
    float* sef = h1t + 4608;          // 2048
    __shared__ int sidx[64];

    int tid = threadIdx.x;
    size_t base = (size_t)blockIdx.x * 32;

    for (int i = tid; i < 512; i += 128)
        ((float4*)sef)[i] = ((const float4*)(ef + base * 64))[i];
    if (tid < 32) {
        sidx[tid] = src[base + tid];
        sidx[32 + tid] = dst[base + tid];
    }
    __syncthreads();

    // gather precomputed A_s[src] + A_d[dst] + ce into g  [32][128]
    {
        const float4* ce4 = (const float4*)g_ce;
#pragma unroll
        for (int m = 0; m < 8; m++) {
            int f = tid + 128 * m;      // float4 index, 0..1023
            int e = f >> 5, c4 = f & 31;
            float4 a = __ldg(&g_As[(size_t)sidx[e] * 32 + c4]);
            float4 b = __ldg(&g_Ad[(size_t)sidx[32 + e] * 32 + c4]);
            float4 c = __ldg(&ce4[c4]);
            float4 r;
            r.x = a.x + b.x + c.x; r.y = a.y + b.y + c.y;
            r.z = a.z + b.z + c.z; r.w = a.w + b.w + c.w;
            ((float4*)g)[f] = r;
        }
    }

    // phase A: pre-edge 64->64, output transposed sxt[k][e]
    {
        int col = tid & 63, hf = tid >> 6;
        float bb = pb[col];
        float acc[16];
#pragma unroll
        for (int i = 0; i < 16; i++) acc[i] = bb;
        const float* xr = sef + hf * 16 * 64;
        for (int k = 0; k < 64; k += 4) {
            float wa = __ldg(pw + k * 64 + col), wb = __ldg(pw + (k + 1) * 64 + col);
            float wc = __ldg(pw + (k + 2) * 64 + col), wd = __ldg(pw + (k + 3) * 64 + col);
#pragma unroll
            for (int i = 0; i < 16; i++) {
                float4 xv = *(const float4*)(xr + i * 64 + k);
                acc[i] = fmaf(xv.x, wa, acc[i]);
                acc[i] = fmaf(xv.y, wb, acc[i]);
                acc[i] = fmaf(xv.z, wc, acc[i]);
                acc[i] = fmaf(xv.w, wd, acc[i]);
            }
        }
#pragma unroll
        for (int i = 0; i < 16; i++)
            sxt[col * 36 + hf * 16 + i] = sp(acc[i]);
    }
    __syncthreads();

    // phase B: L0 e-part 64->128, add gathered g, softplus -> h0t[j][e]
    {
        int j = tid;
        u64 acc[16];
#pragma unroll
        for (int p = 0; p < 16; p++) acc[p] = pack2(0.0f, 0.0f);
#pragma unroll 2
        for (int k = 0; k < 64; k++) {
            float wv = __ldg(w0 + (128 + k) * 128 + j);
            u64 wd = pack2(wv, wv);
            const float* row = sxt + k * 36;
#pragma unroll
            for (int p = 0; p < 8; p++) {
                ulonglong2 xv = *(const ulonglong2*)(row + 4 * p);
                fma2(acc[2 * p], xv.x, wd);
                fma2(acc[2 * p + 1], xv.y, wd);
            }
        }
#pragma unroll
        for (int p = 0; p < 16; p++) {
            float f0, f1;
            unpack2(acc[p], f0, f1);
            f0 += g[(2 * p) * 128 + j];
            f1 += g[(2 * p + 1) * 128 + j];
            h0t[j * 36 + 2 * p] = sp(f0);
            h0t[j * 36 + 2 * p + 1] = sp(f1);
        }
    }
    __syncthreads();

    // phase C: L1 128->128 -> h1t[j][e]
    {
        int j = tid;
        float bb = __ldg(b1 + j);
        u64 acc[16];
#pragma unroll
        for (int p = 0; p < 16; p++) acc[p] = pack2(bb, bb);
#pragma unroll 2
        for (int k = 0; k < 128; k++) {
            float wv = __ldg(w1 + k * 128 + j);
            u64 wd = pack2(wv, wv);
            const float* row = h0t + k * 36;
#pragma unroll
            for (int p = 0; p < 8; p++) {
                ulonglong2 xv = *(const ulonglong2*)(row + 4 * p);
                fma2(acc[2 * p], xv.x, wd);
                fma2(acc[2 * p + 1], xv.y, wd);
            }
        }
#pragma unroll
        for (int p = 0; p < 16; p++) {
            float f0, f1;
            unpack2(acc[p], f0, f1);
            h1t[j * 36 + 2 * p] = sp(f0);
            h1t[j * 36 + 2 * p + 1] = sp(f1);
        }
    }
    __syncthreads();

    // phase D: L2 128->64 split-k; partials into g
    {
        int col = tid & 63, hf = tid >> 6;
        float bb = hf ? 0.0f : __ldg(b2 + col);
        u64 acc[16];
#pragma unroll
        for (int p = 0; p < 16; p++) acc[p] = pack2(bb, bb);
        int k0 = hf * 64;
#pragma unroll 2
        for (int kk = 0; kk < 64; kk++) {
            int k = k0 + kk;
            float wv = __ldg(w2 + k * 64 + col);
            u64 wd = pack2(wv, wv);
            const float* row = h1t + k * 36;
#pragma unroll
            for (int p = 0; p < 8; p++) {
                ulonglong2 xv = *(const ulonglong2*)(row + 4 * p);
                fma2(acc[2 * p], xv.x, wd);
                fma2(acc[2 * p + 1], xv.y, wd);
            }
        }
#pragma unroll
        for (int p = 0; p < 16; p++) {
            float f0, f1;
            unpack2(acc[p], f0, f1);
            g[hf * 2048 + (2 * p) * 64 + col] = f0;
            g[hf * 2048 + (2 * p + 1) * 64 + col] = f1;
        }
    }
    __syncthreads();

    // final: softplus, skip add, segment atomics
    for (int i = tid; i < 2048; i += 128) {
        int e = i >> 6;
        float v = sp(g[i] + g[2048 + i]);
        g[i] = v;
        e_out[base * 64 + i] = v + __ldg(ef + base * 64 + i);
        atomicAdd(&g_ve[(size_t)sidx[32 + e] * 64 + (i & 63)], v);
    }
    if (tid < 32) atomicAdd(&g_cnt[sidx[32 + tid]], 1.0f);
    __syncthreads();
    if (tid < 64) {
        float s = 0.0f;
#pragma unroll
        for (int e = 0; e < 32; e++) s += g[e * 64 + tid];
        atomicAdd(&g_ue[tid], s);
    }
}

// ---------------------------------------------------------------------------
// fused node kernel: 32 nodes / block, 128 threads, f32x2 packed math.
// smem: sxtn 128x36 | h0t 128x36 | h1t 128x36 | part 4096
// ---------------------------------------------------------------------------
__global__ __launch_bounds__(128) void node_kernel(
    const float* __restrict__ nf, const float* __restrict__ w0,
    const float* __restrict__ b1, const float* __restrict__ w1,
    const float* __restrict__ w2, const float* __restrict__ b2,
    float* __restrict__ v_out) {
    extern __shared__ float sm[];
    float* sxtn = sm;               // 128*36 = 4608
    float* h0t  = sm + 4608;        // 4608
    float* h1t  = h0t + 4608;       // 4608
    float* part = h1t + 4608;       // 4096

    int tid = threadIdx.x;
    size_t base = (size_t)blockIdx.x * 32;

    for (int i = tid; i < 2048; i += 128) {
        int n = i >> 6, c = i & 63;
        size_t gn = base + n;
        sxtn[c * 36 + n] = g_v_pre[gn * 64 + c];
        float cn = g_cnt[gn];
        sxtn[(64 + c) * 36 + n] = g_ve[gn * 64 + c] / fmaxf(cn, 1.0f);
    }
    __syncthreads();

    // L0: 128 -> 128 (u folded into g_cn)
    {
        int j = tid;
        float bb = g_cn[j];
        u64 acc[16];
#pragma unroll
        for (int p = 0; p < 16; p++) acc[p] = pack2(bb, bb);
#pragma unroll 2
        for (int k = 0; k < 128; k++) {
            float wv = __ldg(w0 + k * 128 + j);
            u64 wd = pack2(wv, wv);
            const float* row = sxtn + k * 36;
#pragma unroll
            for (int p = 0; p < 8; p++) {
                ulonglong2 xv = *(const ulonglong2*)(row + 4 * p);
                fma2(acc[2 * p], xv.x, wd);
                fma2(acc[2 * p + 1], xv.y, wd);
            }
        }
#pragma unroll
        for (int p = 0; p < 16; p++) {
            float f0, f1;
            unpack2(acc[p], f0, f1);
            h0t[j * 36 + 2 * p] = sp(f0);
            h0t[j * 36 + 2 * p + 1] = sp(f1);
        }
    }
    __syncthreads();

    // L1: 128 -> 128
    {
        int j = tid;
        float bb = __ldg(b1 + j);
        u64 acc[16];
#pragma unroll
        for (int p = 0; p < 16; p++) acc[p] = pack2(bb, bb);
#pragma unroll 2
        for (int k = 0; k < 128; k++) {
            float wv = __ldg(w1 + k * 128 + j);
            u64 wd = pack2(wv, wv);
            const float* row = h0t + k * 36;
#pragma unroll
            for (int p = 0; p < 8; p++) {
                ulonglong2 xv = *(const ulonglong2*)(row + 4 * p);
                fma2(acc[2 * p], xv.x, wd);
                fma2(acc[2 * p + 1], xv.y, wd);
            }
        }
#pragma unroll
        for (int p = 0; p < 16; p++) {
            float f0, f1;
            unpack2(acc[p], f0, f1);
            h1t[j * 36 + 2 * p] = sp(f0);
            h1t[j * 36 + 2 * p + 1] = sp(f1);
        }
    }
    __syncthreads();

    // L2: 128 -> 64 split-k
    {
        int col = tid & 63, hf = tid >> 6;
        float bb = hf ? 0.0f : __ldg(b2 + col);
        u64 acc[16];
#pragma unroll
        for (int p = 0; p < 16; p++) acc[p] = pack2(bb, bb);
        int k0 = hf * 64;
#pragma unroll 2
        for (int kk = 0; kk < 64; kk++) {
            int k = k0 + kk;
            float wv = __ldg(w2 + k * 64 + col);
            u64 wd = pack2(wv, wv);
            const float* row = h1t + k * 36;
#pragma unroll
            for (int p = 0; p < 8; p++) {
                ulonglong2 xv = *(const ulonglong2*)(row + 4 * p);
                fma2(acc[2 * p], xv.x, wd);
                fma2(acc[2 * p + 1], xv.y, wd);
            }
        }
#pragma unroll
        for (int p = 0; p < 16; p++) {
            float f0, f1;
            unpack2(acc[p], f0, f1);
            part[hf * 2048 + (2 * p) * 64 + col] = f0;
            part[hf * 2048 + (2 * p + 1) * 64 + col] = f1;
        }
    }
    __syncthreads();

    for (int i = tid; i < 2048; i += 128) {
        float v = sp(part[i] + part[2048 + i]);
        part[i] = v;
        v_out[base * 64 + i] = v + __ldg(nf + base * 64 + i);
    }
    __syncthreads();
    if (tid < 64) {
        float s = 0.0f;
#pragma unroll
        for (int e = 0; e < 32; e++) s += part[e * 64 + tid];
        atomicAdd(&g_uv[tid], s);
    }
}

// ---------------------------------------------------------------------------
__global__ void attr_kernel(const float* __restrict__ ga,
                            const float* __restrict__ w0,
                            const float* __restrict__ b0,
                            const float* __restrict__ w1,
                            const float* __restrict__ b1,
                            const float* __restrict__ w2,
                            const float* __restrict__ b2,
                            float* __restrict__ out, float invE, float invN) {
    __shared__ float x[192], h0[128], h1[128];
    int t = threadIdx.x;
    if (t < 64) {
        x[t]       = g_u_pre[t];
        x[64 + t]  = g_ue[t] * invE;
        x[128 + t] = g_uv[t] * invN;
    }
    __syncthreads();
    float acc = b0[t];
    for (int k = 0; k < 192; k++) acc = fmaf(x[k], w0[k * 128 + t], acc);
    h0[t] = sp(acc);
    __syncthreads();
    acc = b1[t];
    for (int k = 0; k < 128; k++) acc = fmaf(h0[k], w1[k * 128 + t], acc);
    h1[t] = sp(acc);
    __syncthreads();
    if (t < 64) {
        float a = b2[t];
        for (int k = 0; k < 128; k++) a = fmaf(h1[k], w2[k * 64 + t], a);
        out[t] = sp(a) + ga[t];
    }
}

// ---------------------------------------------------------------------------
extern "C" void kernel_launch(void* const* d_in, const int* in_sizes, int n_in,
                              void* d_out, int out_size) {
    const float* edge_feat  = (const float*)d_in[0];
    const float* node_feat  = (const float*)d_in[1];
    const float* graph_attr = (const float*)d_in[2];
    const int*   src        = (const int*)d_in[3];
    const int*   dst        = (const int*)d_in[4];
    const float* pre_edge_w = (const float*)d_in[5];
    const float* pre_edge_b = (const float*)d_in[6];
    const float* pre_node_w = (const float*)d_in[7];
    const float* pre_node_b = (const float*)d_in[8];
    const float* pre_attr_w = (const float*)d_in[9];
    const float* pre_attr_b = (const float*)d_in[10];
    const float* edge_w0 = (const float*)d_in[11];
    const float* edge_b0 = (const float*)d_in[12];
    const float* edge_w1 = (const float*)d_in[13];
    const float* edge_b1 = (const float*)d_in[14];
    const float* edge_w2 = (const float*)d_in[15];
    const float* edge_b2 = (const float*)d_in[16];
    const float* node_w0 = (const float*)d_in[17];
    const float* node_b0 = (const float*)d_in[18];
    const float* node_w1 = (const float*)d_in[19];
    const float* node_b1 = (const float*)d_in[20];
    const float* node_w2 = (const float*)d_in[21];
    const float* node_b2 = (const float*)d_in[22];
    const float* attr_w0 = (const float*)d_in[23];
    const float* attr_b0 = (const float*)d_in[24];
    const float* attr_w1 = (const float*)d_in[25];
    const float* attr_b1 = (const float*)d_in[26];
    const float* attr_w2 = (const float*)d_in[27];
    const float* attr_b2 = (const float*)d_in[28];

    float* out = (float*)d_out;
    int E = in_sizes[3];
    int N = in_sizes[1] / 64;

    const int edge_smem = (2304 + 4096 + 4608 + 4608 + 2048) * 4;  // 70656
    const int node_smem = (4608 + 4608 + 4608 + 4096) * 4;          // 71680
    cudaFuncSetAttribute(edge_kernel, cudaFuncAttributeMaxDynamicSharedMemorySize,
                         edge_smem);
    cudaFuncSetAttribute(node_kernel, cudaFuncAttributeMaxDynamicSharedMemorySize,
                         node_smem);

    zero_kernel<<<256, 256>>>(N);
    pre_attr_kernel<<<1, 64>>>(graph_attr, pre_attr_w, pre_attr_b);
    const_kernel<<<1, 128>>>(edge_w0, edge_b0, node_w0, node_b0);
    pre_nodeA_kernel<<<N / 32, 128>>>(node_feat, pre_node_w, pre_node_b, edge_w0);
    edge_kernel<<<E / 32, 128, edge_smem>>>(edge_feat, src, dst, pre_edge_w,
                                            pre_edge_b, edge_w0, edge_b1,
                                            edge_w1, edge_w2, edge_b2, out);
    node_kernel<<<N / 32, 128, node_smem>>>(node_feat, node_w0, node_b1, node_w1,
                                            node_w2, node_b2,
                                            out + (size_t)E * 64);
    attr_kernel<<<1, 128>>>(graph_attr, attr_w0, attr_b0, attr_w1, attr_b1,
                            attr_w2, attr_b2,
                            out + (size_t)E * 64 + (size_t)N * 64,
                            1.0f / (float)E, 1.0f / (float)N);
}

// round 5
// speedup vs baseline: 1.7140x; 1.2664x over previous
#include <cuda_runtime.h>
#include <cuda_bf16.h>
#include <mma.h>
#include <cstdint>
#include <cstddef>

using namespace nvcuda;

// ---------------------------------------------------------------------------
// MegNetBlock — wmma bf16 (hi/lo split, 3-pass) fused MLP tiles, sm_100-safe
// N=100000, E=800000, D=64, H=128
// ---------------------------------------------------------------------------

#define NMAX 100000
typedef unsigned int u32;

// ---------------- scratch (device globals) ----------------
__device__ float  g_v_pre[NMAX * 64];
__device__ float4 g_As[NMAX * 32];       // v_pre @ W0e[0:64]    [N,128]
__device__ float4 g_Ad[NMAX * 32];       // v_pre @ W0e[64:128]  [N,128]
__device__ float  g_ve[NMAX * 64];
__device__ float  g_cnt[NMAX];
__device__ float  g_u_pre[64];
__device__ __align__(16) float g_ce[128]; // edge L0 const: eb0 + u@W0e[192:256]
__device__ __align__(16) float g_cn[128]; // node L0 const: nb0 + u@W0n[128:192]
__device__ float  g_ue[64];
__device__ float  g_uv[64];

// bf16 hi/lo split weights, [k][n] row-major per segment (same as source layout)
//  0 Wp   off 0      K=64  N=64
//  1 W0e  off 4096   K=64  N=128   (edge_w0 rows 128..191)
//  2 W1e  off 12288  K=128 N=128
//  3 W2e  off 28672  K=128 N=64
//  4 W0n  off 36864  K=128 N=128   (node_w0 rows 0..127)
//  5 W1n  off 53248  K=128 N=128
//  6 W2n  off 69632  K=128 N=64
__device__ __align__(16) __nv_bfloat16 g_W_h[77824];
__device__ __align__(16) __nv_bfloat16 g_W_l[77824];

// ---------------- smem layout (bytes) ----------------
static constexpr int SA = 136;                 // A stride in bf16 elems
static constexpr int OFF_A_HI = 0;             // 128*136*2 = 34816
static constexpr int OFF_A_LO = 34816;
static constexpr int OFF_W_HI = 69632;         // up to 128*136*2
static constexpr int OFF_W_LO = 104448;
static constexpr int OFF_STG  = 139264;        // 8 warps * 16*20*4 = 10240
static constexpr int OFF_MISC = 149504;        // src 512 | dst 512 | pb 256 | b1 512 | b2 256 | cx 512
static constexpr int SMEM_TOTAL = 152064;

// ---------------- helpers ----------------
__device__ __forceinline__ float sp(float x) {
    return fmaxf(x, 0.0f) + log1pf(expf(-fabsf(x)));
}
__device__ __forceinline__ void split2(float v0, float v1, u32& hi, u32& lo) {
    __nv_bfloat16 h0 = __float2bfloat16(v0), h1 = __float2bfloat16(v1);
    float f0 = __bfloat162float(h0), f1 = __bfloat162float(h1);
    __nv_bfloat16 l0 = __float2bfloat16(v0 - f0), l1 = __float2bfloat16(v1 - f1);
    hi = ((u32)__bfloat16_as_ushort(h1) << 16) | __bfloat16_as_ushort(h0);
    lo = ((u32)__bfloat16_as_ushort(l1) << 16) | __bfloat16_as_ushort(l0);
}

typedef wmma::fragment<wmma::matrix_a, 16, 16, 16, __nv_bfloat16, wmma::row_major> FragA;
typedef wmma::fragment<wmma::matrix_b, 16, 16, 16, __nv_bfloat16, wmma::row_major> FragB;
typedef wmma::fragment<wmma::accumulator, 16, 16, 16, float> FragC;

// one warp computes C[row0:row0+16, 0:N] = A[row0:,:K] @ W[:K,:N], 3-pass hi/lo
__device__ __forceinline__ void layer_mma(const char* smem, int row0, int K, int N,
                                          int SW, FragC* acc) {
    const __nv_bfloat16* Ah = (const __nv_bfloat16*)(smem + OFF_A_HI) + row0 * SA;
    const __nv_bfloat16* Al = (const __nv_bfloat16*)(smem + OFF_A_LO) + row0 * SA;
    const __nv_bfloat16* Wh = (const __nv_bfloat16*)(smem + OFF_W_HI);
    const __nv_bfloat16* Wl = (const __nv_bfloat16*)(smem + OFF_W_LO);
    int nt = N >> 4;
    for (int n = 0; n < nt; n++) wmma::fill_fragment(acc[n], 0.0f);
    for (int k = 0; k < K; k += 16) {
        FragA ah, al;
        wmma::load_matrix_sync(ah, Ah + k, SA);
        wmma::load_matrix_sync(al, Al + k, SA);
        for (int n = 0; n < nt; n++) {
            FragB bh, bl;
            wmma::load_matrix_sync(bh, Wh + k * SW + n * 16, SW);
            wmma::load_matrix_sync(bl, Wl + k * SW + n * 16, SW);
            wmma::mma_sync(acc[n], ah, bh, acc[n]);
            wmma::mma_sync(acc[n], ah, bl, acc[n]);
            wmma::mma_sync(acc[n], al, bh, acc[n]);
        }
    }
}

// cooperative W segment load: global [K][N] hi/lo -> smem stride SW
__device__ __forceinline__ void load_W_smem(char* smem, int off, int K, int N, int SW,
                                            int tid) {
    const u32* gh = (const u32*)(g_W_h + off);
    const u32* gl = (const u32*)(g_W_l + off);
    int total2 = K * N / 2;
    for (int i2 = tid; i2 < total2; i2 += 256) {
        int k = (2 * i2) / N, n = (2 * i2) % N;
        int d = (k * SW + n) * 2;
        *(u32*)(smem + OFF_W_HI + d) = gh[i2];
        *(u32*)(smem + OFF_W_LO + d) = gl[i2];
    }
}

// write 8 fp32 values (pairs) into A hi/lo at (row, col..col+7)
__device__ __forceinline__ void store_A8(char* smem, int row, int col,
                                         const float* v) {
#pragma unroll
    for (int j = 0; j < 8; j += 2) {
        u32 hi, lo;
        split2(v[j], v[j + 1], hi, lo);
        int d = (row * SA + col + j) * 2;
        *(u32*)(smem + OFF_A_HI + d) = hi;
        *(u32*)(smem + OFF_A_LO + d) = lo;
    }
}

// ---------------------------------------------------------------------------
__global__ void zero_kernel(int nNodes) {
    int total = nNodes * 64 + nNodes + 128;
    for (int i = blockIdx.x * blockDim.x + threadIdx.x; i < total;
         i += gridDim.x * blockDim.x) {
        if (i < nNodes * 64) g_ve[i] = 0.0f;
        else if (i < nNodes * 64 + nNodes) g_cnt[i - nNodes * 64] = 0.0f;
        else {
            int j = i - nNodes * 64 - nNodes;
            if (j < 64) g_ue[j] = 0.0f; else g_uv[j - 64] = 0.0f;
        }
    }
}

__global__ void pre_attr_kernel(const float* __restrict__ ga,
                                const float* __restrict__ w,
                                const float* __restrict__ b) {
    __shared__ float sg[64];
    int t = threadIdx.x;
    sg[t] = ga[t];
    __syncthreads();
    float acc = b[t];
    for (int k = 0; k < 64; k++) acc = fmaf(sg[k], w[k * 64 + t], acc);
    g_u_pre[t] = sp(acc);
}

__global__ void const_kernel(const float* __restrict__ ew0,
                             const float* __restrict__ eb0,
                             const float* __restrict__ nw0,
                             const float* __restrict__ nb0) {
    __shared__ float su[64];
    int t = threadIdx.x;  // 128
    if (t < 64) su[t] = g_u_pre[t];
    __syncthreads();
    float a = eb0[t], c = nb0[t];
    for (int k = 0; k < 64; k++) {
        a = fmaf(su[k], ew0[(192 + k) * 128 + t], a);
        c = fmaf(su[k], nw0[(128 + k) * 128 + t], c);
    }
    g_ce[t] = a;
    g_cn[t] = c;
}

// weight hi/lo split (no transpose — [k][n] row-major, as stored)
__global__ void prep_w_kernel(const float* pw, const float* ew0,
                              const float* ew1, const float* ew2,
                              const float* nw0, const float* nw1,
                              const float* nw2) {
    const float* srcs[7] = {pw, ew0 + 128 * 128, ew1, ew2, nw0, nw1, nw2};
    const int KN[7] = {4096, 8192, 16384, 8192, 16384, 16384, 8192};
    const int off[7] = {0, 4096, 12288, 28672, 36864, 53248, 69632};
#pragma unroll 1
    for (int s = 0; s < 7; s++) {
        const float* sc = srcs[s];
        for (int i = blockIdx.x * blockDim.x + threadIdx.x; i < KN[s];
             i += gridDim.x * blockDim.x) {
            float v = sc[i];
            __nv_bfloat16 h = __float2bfloat16(v);
            g_W_h[off[s] + i] = h;
            g_W_l[off[s] + i] = __float2bfloat16(v - __bfloat162float(h));
        }
    }
}

// ---------------------------------------------------------------------------
// pre-node + per-node precompute (fp32 SIMT, ~160us)
// ---------------------------------------------------------------------------
__global__ __launch_bounds__(128) void pre_nodeA_kernel(
    const float* __restrict__ nf, const float* __restrict__ pw,
    const float* __restrict__ pb, const float* __restrict__ ew0) {
    __shared__ float snf[2048];
    __shared__ float sv[2048];
    int tid = threadIdx.x;
    size_t base = (size_t)blockIdx.x * 32;

    for (int i = tid; i < 512; i += 128)
        ((float4*)snf)[i] = ((const float4*)(nf + base * 64))[i];
    __syncthreads();

    {
        int col = tid & 63, hf = tid >> 6;
        float bb = pb[col];
        float acc[16];
#pragma unroll
        for (int i = 0; i < 16; i++) acc[i] = bb;
        const float* xr = snf + hf * 16 * 64;
        for (int k = 0; k < 64; k += 4) {
            float wa = __ldg(pw + k * 64 + col), wb = __ldg(pw + (k + 1) * 64 + col);
            float wc = __ldg(pw + (k + 2) * 64 + col), wd = __ldg(pw + (k + 3) * 64 + col);
#pragma unroll
            for (int i = 0; i < 16; i++) {
                float4 xv = *(const float4*)(xr + i * 64 + k);
                acc[i] = fmaf(xv.x, wa, acc[i]);
                acc[i] = fmaf(xv.y, wb, acc[i]);
                acc[i] = fmaf(xv.z, wc, acc[i]);
                acc[i] = fmaf(xv.w, wd, acc[i]);
            }
        }
#pragma unroll
        for (int i = 0; i < 16; i++) {
            float v = sp(acc[i]);
            sv[(hf * 16 + i) * 64 + col] = v;
            g_v_pre[(base + hf * 16 + i) * 64 + col] = v;
        }
    }
    __syncthreads();

    float* Asf = (float*)g_As;
    float* Adf = (float*)g_Ad;
    int j = tid;
#pragma unroll 1
    for (int m = 0; m < 2; m++) {
        const float* w = ew0 + (size_t)m * 64 * 128;
        float acc[32];
#pragma unroll
        for (int e = 0; e < 32; e++) acc[e] = 0.0f;
        for (int k = 0; k < 64; k += 4) {
            float wa = __ldg(w + k * 128 + j), wb = __ldg(w + (k + 1) * 128 + j);
            float wc = __ldg(w + (k + 2) * 128 + j), wd = __ldg(w + (k + 3) * 128 + j);
#pragma unroll
            for (int e = 0; e < 32; e++) {
                float4 xv = *(const float4*)(sv + e * 64 + k);
                acc[e] = fmaf(xv.x, wa, acc[e]);
                acc[e] = fmaf(xv.y, wb, acc[e]);
                acc[e] = fmaf(xv.z, wc, acc[e]);
                acc[e] = fmaf(xv.w, wd, acc[e]);
            }
        }
        float* dstp = m ? Adf : Asf;
#pragma unroll
        for (int e = 0; e < 32; e++) dstp[(base + e) * 128 + j] = acc[e];
    }
}

// ---------------------------------------------------------------------------
// fused edge kernel: 128 edges / CTA, 256 threads (8 warps x 16-row slabs)
// ---------------------------------------------------------------------------
__global__ __launch_bounds__(256) void edge_kernel(
    const float* __restrict__ ef, const int* __restrict__ srcI,
    const int* __restrict__ dstI, const float* __restrict__ pb,
    const float* __restrict__ b1, const float* __restrict__ b2,
    float* __restrict__ e_out) {
    extern __shared__ char smem[];
    int tid = threadIdx.x;
    int wid = tid >> 5, lane = tid & 31;
    size_t base = (size_t)blockIdx.x * 128;

    int* s_src = (int*)(smem + OFF_MISC);
    int* s_dst = (int*)(smem + OFF_MISC + 512);
    float* s_pb = (float*)(smem + OFF_MISC + 1024);
    float* s_b1 = (float*)(smem + OFF_MISC + 1280);
    float* s_b2 = (float*)(smem + OFF_MISC + 1792);
    float* s_ce = (float*)(smem + OFF_MISC + 2048);
    float* stg = (float*)(smem + OFF_STG) + wid * 320;  // 16x20

    if (tid < 128) {
        s_src[tid] = srcI[base + tid];
        s_dst[tid] = dstI[base + tid];
        s_ce[tid] = g_ce[tid];
        s_b1[tid] = __ldg(b1 + tid);
    } else if (tid < 192) {
        s_pb[tid - 128] = __ldg(pb + tid - 128);
    } else {
        s_b2[tid - 192] = __ldg(b2 + tid - 192);
    }

    // stage ef -> A hi/lo (rows 0..127, cols 0..63)
    {
        int r = tid >> 1, h = tid & 1;
        const float4* g4 = (const float4*)(ef + (base + r) * 64 + h * 32);
#pragma unroll
        for (int q = 0; q < 8; q++) {
            float4 v = __ldg(g4 + q);
            float vv[4] = {v.x, v.y, v.z, v.w};
            int c = h * 32 + q * 4;
            u32 hi, lo;
            split2(vv[0], vv[1], hi, lo);
            *(u32*)(smem + OFF_A_HI + (r * SA + c) * 2) = hi;
            *(u32*)(smem + OFF_A_LO + (r * SA + c) * 2) = lo;
            split2(vv[2], vv[3], hi, lo);
            *(u32*)(smem + OFF_A_HI + (r * SA + c + 2) * 2) = hi;
            *(u32*)(smem + OFF_A_LO + (r * SA + c + 2) * 2) = lo;
        }
    }
    load_W_smem(smem, 0, 64, 64, 72, tid);  // Wp
    __syncthreads();

    int row0 = wid * 16;
    int r = lane >> 1, c0 = (lane & 1) * 8;
    int row = row0 + r;
    FragC acc[8];

    // ---- phase 0: pre-edge  K=64 N=64 ----
    layer_mma(smem, row0, 64, 64, 72, acc);
#pragma unroll
    for (int n = 0; n < 4; n++) {
        wmma::store_matrix_sync(stg, acc[n], 20, wmma::mem_row_major);
        __syncwarp();
        int col = n * 16 + c0;
        float v[8];
#pragma unroll
        for (int j = 0; j < 8; j++) v[j] = sp(stg[r * 20 + c0 + j] + s_pb[col + j]);
        store_A8(smem, row, col, v);
        __syncwarp();
    }
    __syncthreads();
    load_W_smem(smem, 4096, 64, 128, 136, tid);  // W0e (e-part)
    __syncthreads();

    // ---- phase 1: L0  K=64 N=128  (+ As[src]+Ad[dst]+ce in fp32) ----
    layer_mma(smem, row0, 64, 128, 136, acc);
    {
        const float4* as4 = (const float4*)g_As + (size_t)s_src[row] * 32;
        const float4* ad4 = (const float4*)g_Ad + (size_t)s_dst[row] * 32;
#pragma unroll
        for (int n = 0; n < 8; n++) {
            wmma::store_matrix_sync(stg, acc[n], 20, wmma::mem_row_major);
            __syncwarp();
            int col = n * 16 + c0;
            float4 a0 = __ldg(as4 + (col >> 2)), a1 = __ldg(as4 + (col >> 2) + 1);
            float4 d0 = __ldg(ad4 + (col >> 2)), d1 = __ldg(ad4 + (col >> 2) + 1);
            float ga[8] = {a0.x + d0.x, a0.y + d0.y, a0.z + d0.z, a0.w + d0.w,
                           a1.x + d1.x, a1.y + d1.y, a1.z + d1.z, a1.w + d1.w};
            float v[8];
#pragma unroll
            for (int j = 0; j < 8; j++)
                v[j] = sp(stg[r * 20 + c0 + j] + ga[j] + s_ce[col + j]);
            store_A8(smem, row, col, v);
            __syncwarp();
        }
    }
    __syncthreads();
    load_W_smem(smem, 12288, 128, 128, 136, tid);  // W1e
    __syncthreads();

    // ---- phase 2: L1  K=128 N=128 ----
    layer_mma(smem, row0, 128, 128, 136, acc);
#pragma unroll
    for (int n = 0; n < 8; n++) {
        wmma::store_matrix_sync(stg, acc[n], 20, wmma::mem_row_major);
        __syncwarp();
        int col = n * 16 + c0;
        float v[8];
#pragma unroll
        for (int j = 0; j < 8; j++) v[j] = sp(stg[r * 20 + c0 + j] + s_b1[col + j]);
        store_A8(smem, row, col, v);
        __syncwarp();
    }
    __syncthreads();
    load_W_smem(smem, 28672, 128, 64, 72, tid);  // W2e
    __syncthreads();

    // ---- phase 3: L2  K=128 N=64 ----
    layer_mma(smem, row0, 128, 64, 72, acc);
    {
        float* fstage = (float*)(smem + OFF_A_HI);  // reuse own slab as f32 [128][68]
        int dnode = s_dst[row];
#pragma unroll
        for (int n = 0; n < 4; n++) {
            wmma::store_matrix_sync(stg, acc[n], 20, wmma::mem_row_major);
            __syncwarp();
            int col = n * 16 + c0;
            float v[8];
#pragma unroll
            for (int j = 0; j < 8; j++) v[j] = sp(stg[r * 20 + c0 + j] + s_b2[col + j]);
            size_t gidx = (base + row) * 64 + col;
            float4 e0 = __ldg((const float4*)(ef + gidx));
            float4 e1 = __ldg((const float4*)(ef + gidx) + 1);
            float4 o0 = {v[0] + e0.x, v[1] + e0.y, v[2] + e0.z, v[3] + e0.w};
            float4 o1 = {v[4] + e1.x, v[5] + e1.y, v[6] + e1.z, v[7] + e1.w};
            *(float4*)(e_out + gidx) = o0;
            *((float4*)(e_out + gidx) + 1) = o1;
            float* vrow = &g_ve[(size_t)dnode * 64 + col];
#pragma unroll
            for (int j = 0; j < 8; j++) {
                atomicAdd(vrow + j, v[j]);
                fstage[row * 68 + col + j] = v[j];
            }
            if (n == 0 && (lane & 1) == 0) atomicAdd(&g_cnt[dnode], 1.0f);
            __syncwarp();
        }
    }
    __syncthreads();
    if (tid < 64) {
        float* fstage = (float*)(smem + OFF_A_HI);
        float s = 0.0f;
        for (int rr = 0; rr < 128; rr++) s += fstage[rr * 68 + tid];
        atomicAdd(&g_ue[tid], s);
    }
}

// ---------------------------------------------------------------------------
// fused node kernel: 128 nodes / CTA, 256 threads (tail-masked)
// ---------------------------------------------------------------------------
__global__ __launch_bounds__(256) void node_kernel(
    const float* __restrict__ nf, const float* __restrict__ b1,
    const float* __restrict__ b2, float* __restrict__ v_out, int nNodes) {
    extern __shared__ char smem[];
    int tid = threadIdx.x;
    int wid = tid >> 5, lane = tid & 31;
    size_t base = (size_t)blockIdx.x * 128;

    float* s_b1 = (float*)(smem + OFF_MISC + 1280);
    float* s_b2 = (float*)(smem + OFF_MISC + 1792);
    float* s_cn = (float*)(smem + OFF_MISC + 2048);
    float* stg = (float*)(smem + OFF_STG) + wid * 320;

    if (tid < 128) {
        s_cn[tid] = g_cn[tid];
        s_b1[tid] = __ldg(b1 + tid);
    } else if (tid >= 192) {
        s_b2[tid - 192] = __ldg(b2 + tid - 192);
    }

    // stage X = [v_pre | ve_mean] (K=128)
    {
        int r = tid >> 1, h = tid & 1;
        size_t gn = base + r;
        if (gn >= (size_t)nNodes) gn = nNodes - 1;
        const float4* g4;
        float scale = 1.0f;
        if (h == 0) {
            g4 = (const float4*)(g_v_pre + gn * 64);
        } else {
            g4 = (const float4*)(g_ve + gn * 64);
            scale = 1.0f / fmaxf(g_cnt[gn], 1.0f);
        }
#pragma unroll
        for (int q = 0; q < 16; q++) {
            float4 v = __ldg(g4 + q);
            v.x *= scale; v.y *= scale; v.z *= scale; v.w *= scale;
            int c = h * 64 + q * 4;
            u32 hi, lo;
            split2(v.x, v.y, hi, lo);
            *(u32*)(smem + OFF_A_HI + (r * SA + c) * 2) = hi;
            *(u32*)(smem + OFF_A_LO + (r * SA + c) * 2) = lo;
            split2(v.z, v.w, hi, lo);
            *(u32*)(smem + OFF_A_HI + (r * SA + c + 2) * 2) = hi;
            *(u32*)(smem + OFF_A_LO + (r * SA + c + 2) * 2) = lo;
        }
    }
    load_W_smem(smem, 36864, 128, 128, 136, tid);  // W0n
    __syncthreads();

    int row0 = wid * 16;
    int r = lane >> 1, c0 = (lane & 1) * 8;
    int row = row0 + r;
    bool valid = (base + row) < (size_t)nNodes;
    FragC acc[8];

    // ---- L0  K=128 N=128 (bias = cn, u folded) ----
    layer_mma(smem, row0, 128, 128, 136, acc);
#pragma unroll
    for (int n = 0; n < 8; n++) {
        wmma::store_matrix_sync(stg, acc[n], 20, wmma::mem_row_major);
        __syncwarp();
        int col = n * 16 + c0;
        float v[8];
#pragma unroll
        for (int j = 0; j < 8; j++) v[j] = sp(stg[r * 20 + c0 + j] + s_cn[col + j]);
        store_A8(smem, row, col, v);
        __syncwarp();
    }
    __syncthreads();
    load_W_smem(smem, 53248, 128, 128, 136, tid);  // W1n
    __syncthreads();

    // ---- L1  K=128 N=128 ----
    layer_mma(smem, row0, 128, 128, 136, acc);
#pragma unroll
    for (int n = 0; n < 8; n++) {
        wmma::store_matrix_sync(stg, acc[n], 20, wmma::mem_row_major);
        __syncwarp();
        int col = n * 16 + c0;
        float v[8];
#pragma unroll
        for (int j = 0; j < 8; j++) v[j] = sp(stg[r * 20 + c0 + j] + s_b1[col + j]);
        store_A8(smem, row, col, v);
        __syncwarp();
    }
    __syncthreads();
    load_W_smem(smem, 69632, 128, 64, 72, tid);  // W2n
    __syncthreads();

    // ---- L2  K=128 N=64 ----
    layer_mma(smem, row0, 128, 64, 72, acc);
    {
        float* fstage = (float*)(smem + OFF_A_HI);  // f32 [128][68]
#pragma unroll
        for (int n = 0; n < 4; n++) {
            wmma::store_matrix_sync(stg, acc[n], 20, wmma::mem_row_major);
            __syncwarp();
            int col = n * 16 + c0;
            float v[8];
#pragma unroll
            for (int j = 0; j < 8; j++) v[j] = sp(stg[r * 20 + c0 + j] + s_b2[col + j]);
            if (valid) {
                size_t gidx = (base + row) * 64 + col;
                float4 e0 = __ldg((const float4*)(nf + gidx));
                float4 e1 = __ldg((const float4*)(nf + gidx) + 1);
                float4 o0 = {v[0] + e0.x, v[1] + e0.y, v[2] + e0.z, v[3] + e0.w};
                float4 o1 = {v[4] + e1.x, v[5] + e1.y, v[6] + e1.z, v[7] + e1.w};
                *(float4*)(v_out + gidx) = o0;
                *((float4*)(v_out + gidx) + 1) = o1;
            }
#pragma unroll
            for (int j = 0; j < 8; j++)
                fstage[row * 68 + col + j] = valid ? v[j] : 0.0f;
            __syncwarp();
        }
    }
    __syncthreads();
    if (tid < 64) {
        float* fstage = (float*)(smem + OFF_A_HI);
        float s = 0.0f;
        for (int rr = 0; rr < 128; rr++) s += fstage[rr * 68 + tid];
        atomicAdd(&g_uv[tid], s);
    }
}

// ---------------------------------------------------------------------------
__global__ void attr_kernel(const float* __restrict__ ga,
                            const float* __restrict__ w0,
                            const float* __restrict__ b0,
                            const float* __restrict__ w1,
                            const float* __restrict__ b1,
                            const float* __restrict__ w2,
                            const float* __restrict__ b2,
                            float* __restrict__ out, float invE, float invN) {
    __shared__ float x[192], h0[128], h1[128];
    int t = threadIdx.x;
    if (t < 64) {
        x[t]       = g_u_pre[t];
        x[64 + t]  = g_ue[t] * invE;
        x[128 + t] = g_uv[t] * invN;
    }
    __syncthreads();
    float acc = b0[t];
    for (int k = 0; k < 192; k++) acc = fmaf(x[k], w0[k * 128 + t], acc);
    h0[t] = sp(acc);
    __syncthreads();
    acc = b1[t];
    for (int k = 0; k < 128; k++) acc = fmaf(h0[k], w1[k * 128 + t], acc);
    h1[t] = sp(acc);
    __syncthreads();
    if (t < 64) {
        float a = b2[t];
        for (int k = 0; k < 128; k++) a = fmaf(h1[k], w2[k * 64 + t], a);
        out[t] = sp(a) + ga[t];
    }
}

// ---------------------------------------------------------------------------
extern "C" void kernel_launch(void* const* d_in, const int* in_sizes, int n_in,
                              void* d_out, int out_size) {
    const float* edge_feat  = (const float*)d_in[0];
    const float* node_feat  = (const float*)d_in[1];
    const float* graph_attr = (const float*)d_in[2];
    const int*   src        = (const int*)d_in[3];
    const int*   dst        = (const int*)d_in[4];
    const float* pre_edge_w = (const float*)d_in[5];
    const float* pre_edge_b = (const float*)d_in[6];
    const float* pre_node_w = (const float*)d_in[7];
    const float* pre_node_b = (const float*)d_in[8];
    const float* pre_attr_w = (const float*)d_in[9];
    const float* pre_attr_b = (const float*)d_in[10];
    const float* edge_w0 = (const float*)d_in[11];
    const float* edge_b0 = (const float*)d_in[12];
    const float* edge_w1 = (const float*)d_in[13];
    const float* edge_b1 = (const float*)d_in[14];
    const float* edge_w2 = (const float*)d_in[15];
    const float* edge_b2 = (const float*)d_in[16];
    const float* node_w0 = (const float*)d_in[17];
    const float* node_b0 = (const float*)d_in[18];
    const float* node_w1 = (const float*)d_in[19];
    const float* node_b1 = (const float*)d_in[20];
    const float* node_w2 = (const float*)d_in[21];
    const float* node_b2 = (const float*)d_in[22];
    const float* attr_w0 = (const float*)d_in[23];
    const float* attr_b0 = (const float*)d_in[24];
    const float* attr_w1 = (const float*)d_in[25];
    const float* attr_b1 = (const float*)d_in[26];
    const float* attr_w2 = (const float*)d_in[27];
    const float* attr_b2 = (const float*)d_in[28];

    float* out = (float*)d_out;
    int E = in_sizes[3];
    int N = in_sizes[1] / 64;

    cudaFuncSetAttribute(edge_kernel, cudaFuncAttributeMaxDynamicSharedMemorySize,
                         SMEM_TOTAL);
    cudaFuncSetAttribute(node_kernel, cudaFuncAttributeMaxDynamicSharedMemorySize,
                         SMEM_TOTAL);

    zero_kernel<<<256, 256>>>(N);
    pre_attr_kernel<<<1, 64>>>(graph_attr, pre_attr_w, pre_attr_b);
    const_kernel<<<1, 128>>>(edge_w0, edge_b0, node_w0, node_b0);
    prep_w_kernel<<<64, 256>>>(pre_edge_w, edge_w0, edge_w1, edge_w2, node_w0,
                               node_w1, node_w2);
    pre_nodeA_kernel<<<N / 32, 128>>>(node_feat, pre_node_w, pre_node_b, edge_w0);
    edge_kernel<<<E / 128, 256, SMEM_TOTAL>>>(edge_feat, src, dst, pre_edge_b,
                                              edge_b1, edge_b2, out);
    node_kernel<<<(N + 127) / 128, 256, SMEM_TOTAL>>>(node_feat, node_b1, node_b2,
                                                      out + (size_t)E * 64, N);
    attr_kernel<<<1, 128>>>(graph_attr, attr_w0, attr_b0, attr_w1, attr_b1,
                            attr_w2, attr_b2,
                            out + (size_t)E * 64 + (size_t)N * 64,
                            1.0f / (float)E, 1.0f / (float)N);
}

// round 6
// speedup vs baseline: 2.1355x; 1.2459x over previous
#include <cuda_runtime.h>
#include <cuda_bf16.h>
#include <mma.h>
#include <cstdint>
#include <cstddef>

using namespace nvcuda;

// ---------------------------------------------------------------------------
// MegNetBlock — persistent wmma bf16 (hi/lo 3-pass), weights resident in smem
// N=100000, E=800000, D=64, H=128
// ---------------------------------------------------------------------------

#define NMAX 100000
typedef unsigned int u32;

// ---------------- scratch (device globals) ----------------
__device__ float  g_v_pre[NMAX * 64];
__device__ float4 g_As[NMAX * 32];       // v_pre @ W0e[0:64]    [N,128]
__device__ float4 g_Ad[NMAX * 32];       // v_pre @ W0e[64:128]  [N,128]
__device__ float  g_ve[NMAX * 64];
__device__ float  g_cnt[NMAX];
__device__ float  g_u_pre[64];
__device__ __align__(16) float g_ce[128]; // edge L0 const: eb0 + u@W0e[192:256]
__device__ __align__(16) float g_cn[128]; // node L0 const: nb0 + u@W0n[128:192]
__device__ float  g_ue[64];
__device__ float  g_uv[64];

// bf16 hi/lo split weights, [k][n] row-major per segment
//  0 Wp   off 0      K=64  N=64
//  1 W0e  off 4096   K=64  N=128   (edge_w0 rows 128..191)
//  2 W1e  off 12288  K=128 N=128
//  3 W2e  off 28672  K=128 N=64
//  4 W0n  off 36864  K=128 N=128   (node_w0 rows 0..127)
//  5 W1n  off 53248  K=128 N=128
//  6 W2n  off 69632  K=128 N=64
__device__ __align__(16) __nv_bfloat16 g_W_h[77824];
__device__ __align__(16) __nv_bfloat16 g_W_l[77824];

// ---------------- smem layouts (byte offsets) ----------------
static constexpr int SA = 136;   // A row stride in bf16 elems

// edge kernel
static constexpr int E_WP_H = 0;        // 64x72
static constexpr int E_WP_L = 9216;
static constexpr int E_W0_H = 18432;    // 64x136
static constexpr int E_W0_L = 35840;
static constexpr int E_W1_H = 53248;    // 128x136
static constexpr int E_W1_L = 88064;
static constexpr int E_W2_H = 122880;   // 128x72
static constexpr int E_W2_L = 141312;
static constexpr int E_A_H  = 159744;   // 64x136
static constexpr int E_A_L  = 177152;
static constexpr int E_STG  = 194560;   // 8 warps x 16x20 f32
static constexpr int E_MISC = 204800;   // src|dst|pb|b1|b2|ce|spart
static constexpr int E_TOTAL = 207872;

// node kernel
static constexpr int N_W0_H = 0;        // 128x136
static constexpr int N_W0_L = 34816;
static constexpr int N_W1_H = 69632;
static constexpr int N_W1_L = 104448;
static constexpr int N_W2_H = 139264;   // 128x72
static constexpr int N_W2_L = 157696;
static constexpr int N_A_H  = 176128;
static constexpr int N_A_L  = 193536;
static constexpr int N_STG  = 210944;
static constexpr int N_MISC = 221184;   // cn|b1|b2|spart
static constexpr int N_TOTAL = 223744;

static constexpr int NUM_CTAS = 148;

// ---------------- helpers ----------------
__device__ __forceinline__ float sp(float x) {
    return fmaxf(x, 0.0f) + log1pf(expf(-fabsf(x)));
}
__device__ __forceinline__ void split2(float v0, float v1, u32& hi, u32& lo) {
    __nv_bfloat16 h0 = __float2bfloat16(v0), h1 = __float2bfloat16(v1);
    float f0 = __bfloat162float(h0), f1 = __bfloat162float(h1);
    __nv_bfloat16 l0 = __float2bfloat16(v0 - f0), l1 = __float2bfloat16(v1 - f1);
    hi = ((u32)__bfloat16_as_ushort(h1) << 16) | __bfloat16_as_ushort(h0);
    lo = ((u32)__bfloat16_as_ushort(l1) << 16) | __bfloat16_as_ushort(l0);
}

typedef wmma::fragment<wmma::matrix_a, 16, 16, 16, __nv_bfloat16, wmma::row_major> FragA;
typedef wmma::fragment<wmma::matrix_b, 16, 16, 16, __nv_bfloat16, wmma::row_major> FragB;
typedef wmma::fragment<wmma::accumulator, 16, 16, 16, float> FragC;

// one warp: C[row0:16, colbase:colbase+nt*16] = A[row0:, :K] @ W[:, cols], 3-pass
__device__ __forceinline__ void mma_half(const char* smem, int offAh, int offAl,
                                         int offWh, int offWl, int row0, int K,
                                         int SW, int colbase, int nt, FragC* acc) {
    const __nv_bfloat16* Ah = (const __nv_bfloat16*)(smem + offAh) + row0 * SA;
    const __nv_bfloat16* Al = (const __nv_bfloat16*)(smem + offAl) + row0 * SA;
    const __nv_bfloat16* Wh = (const __nv_bfloat16*)(smem + offWh) + colbase;
    const __nv_bfloat16* Wl = (const __nv_bfloat16*)(smem + offWl) + colbase;
    for (int n = 0; n < nt; n++) wmma::fill_fragment(acc[n], 0.0f);
    for (int k = 0; k < K; k += 16) {
        FragA ah, al;
        wmma::load_matrix_sync(ah, Ah + k, SA);
        wmma::load_matrix_sync(al, Al + k, SA);
        for (int n = 0; n < nt; n++) {
            FragB bh, bl;
            wmma::load_matrix_sync(bh, Wh + k * SW + n * 16, SW);
            wmma::load_matrix_sync(bl, Wl + k * SW + n * 16, SW);
            wmma::mma_sync(acc[n], ah, bh, acc[n]);
            wmma::mma_sync(acc[n], ah, bl, acc[n]);
            wmma::mma_sync(acc[n], al, bh, acc[n]);
        }
    }
}

// one-time cooperative W segment load: global [K][N] -> smem stride SW
__device__ __forceinline__ void load_W_seg(char* smem, int goff, int K, int N, int SW,
                                           int offh, int offl, int tid) {
    const u32* gh = (const u32*)(g_W_h + goff);
    const u32* gl = (const u32*)(g_W_l + goff);
    int total2 = K * N / 2;
    for (int i2 = tid; i2 < total2; i2 += 256) {
        int k = (2 * i2) / N, n = (2 * i2) % N;
        int d = (k * SW + n) * 2;
        *(u32*)(smem + offh + d) = gh[i2];
        *(u32*)(smem + offl + d) = gl[i2];
    }
}

__device__ __forceinline__ void store_A8(char* smem, int offAh, int offAl, int row,
                                         int col, const float* v) {
#pragma unroll
    for (int j = 0; j < 8; j += 2) {
        u32 hi, lo;
        split2(v[j], v[j + 1], hi, lo);
        int d = (row * SA + col + j) * 2;
        *(u32*)(smem + offAh + d) = hi;
        *(u32*)(smem + offAl + d) = lo;
    }
}

// ---------------------------------------------------------------------------
__global__ void zero_kernel(int nNodes) {
    int total = nNodes * 64 + nNodes + 128;
    for (int i = blockIdx.x * blockDim.x + threadIdx.x; i < total;
         i += gridDim.x * blockDim.x) {
        if (i < nNodes * 64) g_ve[i] = 0.0f;
        else if (i < nNodes * 64 + nNodes) g_cnt[i - nNodes * 64] = 0.0f;
        else {
            int j = i - nNodes * 64 - nNodes;
            if (j < 64) g_ue[j] = 0.0f; else g_uv[j - 64] = 0.0f;
        }
    }
}

__global__ void pre_attr_kernel(const float* __restrict__ ga,
                                const float* __restrict__ w,
                                const float* __restrict__ b) {
    __shared__ float sg[64];
    int t = threadIdx.x;
    sg[t] = ga[t];
    __syncthreads();
    float acc = b[t];
    for (int k = 0; k < 64; k++) acc = fmaf(sg[k], w[k * 64 + t], acc);
    g_u_pre[t] = sp(acc);
}

__global__ void const_kernel(const float* __restrict__ ew0,
                             const float* __restrict__ eb0,
                             const float* __restrict__ nw0,
                             const float* __restrict__ nb0) {
    __shared__ float su[64];
    int t = threadIdx.x;  // 128
    if (t < 64) su[t] = g_u_pre[t];
    __syncthreads();
    float a = eb0[t], c = nb0[t];
    for (int k = 0; k < 64; k++) {
        a = fmaf(su[k], ew0[(192 + k) * 128 + t], a);
        c = fmaf(su[k], nw0[(128 + k) * 128 + t], c);
    }
    g_ce[t] = a;
    g_cn[t] = c;
}

__global__ void prep_w_kernel(const float* pw, const float* ew0,
                              const float* ew1, const float* ew2,
                              const float* nw0, const float* nw1,
                              const float* nw2) {
    const float* srcs[7] = {pw, ew0 + 128 * 128, ew1, ew2, nw0, nw1, nw2};
    const int KN[7] = {4096, 8192, 16384, 8192, 16384, 16384, 8192};
    const int off[7] = {0, 4096, 12288, 28672, 36864, 53248, 69632};
#pragma unroll 1
    for (int s = 0; s < 7; s++) {
        const float* sc = srcs[s];
        for (int i = blockIdx.x * blockDim.x + threadIdx.x; i < KN[s];
             i += gridDim.x * blockDim.x) {
            float v = sc[i];
            __nv_bfloat16 h = __float2bfloat16(v);
            g_W_h[off[s] + i] = h;
            g_W_l[off[s] + i] = __float2bfloat16(v - __bfloat162float(h));
        }
    }
}

// ---------------------------------------------------------------------------
// pre-node + per-node precompute (fp32 SIMT)
// ---------------------------------------------------------------------------
__global__ __launch_bounds__(128) void pre_nodeA_kernel(
    const float* __restrict__ nf, const float* __restrict__ pw,
    const float* __restrict__ pb, const float* __restrict__ ew0) {
    __shared__ float snf[2048];
    __shared__ float sv[2048];
    int tid = threadIdx.x;
    size_t base = (size_t)blockIdx.x * 32;

    for (int i = tid; i < 512; i += 128)
        ((float4*)snf)[i] = ((const float4*)(nf + base * 64))[i];
    __syncthreads();

    {
        int col = tid & 63, hf = tid >> 6;
        float bb = pb[col];
        float acc[16];
#pragma unroll
        for (int i = 0; i < 16; i++) acc[i] = bb;
        const float* xr = snf + hf * 16 * 64;
        for (int k = 0; k < 64; k += 4) {
            float wa = __ldg(pw + k * 64 + col), wb = __ldg(pw + (k + 1) * 64 + col);
            float wc = __ldg(pw + (k + 2) * 64 + col), wd = __ldg(pw + (k + 3) * 64 + col);
#pragma unroll
            for (int i = 0; i < 16; i++) {
                float4 xv = *(const float4*)(xr + i * 64 + k);
                acc[i] = fmaf(xv.x, wa, acc[i]);
                acc[i] = fmaf(xv.y, wb, acc[i]);
                acc[i] = fmaf(xv.z, wc, acc[i]);
                acc[i] = fmaf(xv.w, wd, acc[i]);
            }
        }
#pragma unroll
        for (int i = 0; i < 16; i++) {
            float v = sp(acc[i]);
            sv[(hf * 16 + i) * 64 + col] = v;
            g_v_pre[(base + hf * 16 + i) * 64 + col] = v;
        }
    }
    __syncthreads();

    float* Asf = (float*)g_As;
    float* Adf = (float*)g_Ad;
    int j = tid;
#pragma unroll 1
    for (int m = 0; m < 2; m++) {
        const float* w = ew0 + (size_t)m * 64 * 128;
        float acc[32];
#pragma unroll
        for (int e = 0; e < 32; e++) acc[e] = 0.0f;
        for (int k = 0; k < 64; k += 4) {
            float wa = __ldg(w + k * 128 + j), wb = __ldg(w + (k + 1) * 128 + j);
            float wc = __ldg(w + (k + 2) * 128 + j), wd = __ldg(w + (k + 3) * 128 + j);
#pragma unroll
            for (int e = 0; e < 32; e++) {
                float4 xv = *(const float4*)(sv + e * 64 + k);
                acc[e] = fmaf(xv.x, wa, acc[e]);
                acc[e] = fmaf(xv.y, wb, acc[e]);
                acc[e] = fmaf(xv.z, wc, acc[e]);
                acc[e] = fmaf(xv.w, wd, acc[e]);
            }
        }
        float* dstp = m ? Adf : Asf;
#pragma unroll
        for (int e = 0; e < 32; e++) dstp[(base + e) * 128 + j] = acc[e];
    }
}

// ---------------------------------------------------------------------------
// persistent fused edge kernel: 64 edges / iteration, weights resident
// ---------------------------------------------------------------------------
__global__ __launch_bounds__(256) void edge_kernel(
    const float* __restrict__ ef, const int* __restrict__ srcI,
    const int* __restrict__ dstI, const float* __restrict__ pb,
    const float* __restrict__ b1, const float* __restrict__ b2,
    float* __restrict__ e_out, int nTiles) {
    extern __shared__ char smem[];
    int tid = threadIdx.x, wid = tid >> 5, lane = tid & 31;

    int*   s_src = (int*)(smem + E_MISC);
    int*   s_dst = (int*)(smem + E_MISC + 256);
    float* s_pb  = (float*)(smem + E_MISC + 512);
    float* s_b1  = (float*)(smem + E_MISC + 768);
    float* s_b2  = (float*)(smem + E_MISC + 1280);
    float* s_ce  = (float*)(smem + E_MISC + 1536);
    float* spart = (float*)(smem + E_MISC + 2048);
    float* stg   = (float*)(smem + E_STG) + wid * 320;
    float* fstage = (float*)(smem + E_A_H);  // f32 [64][68], reused post-MMA

    // one-time: weights + biases
    load_W_seg(smem, 0,     64, 64,  72, E_WP_H, E_WP_L, tid);
    load_W_seg(smem, 4096,  64, 128, 136, E_W0_H, E_W0_L, tid);
    load_W_seg(smem, 12288, 128, 128, 136, E_W1_H, E_W1_L, tid);
    load_W_seg(smem, 28672, 128, 64,  72, E_W2_H, E_W2_L, tid);
    if (tid < 128) {
        s_ce[tid] = g_ce[tid];
        s_b1[tid] = __ldg(b1 + tid);
    } else if (tid < 192) {
        s_pb[tid - 128] = __ldg(pb + tid - 128);
    } else {
        s_b2[tid - 192] = __ldg(b2 + tid - 192);
    }

    int slab = wid & 3, h = wid >> 2, row0 = slab * 16;
    int r = lane >> 1, c0 = (lane & 1) * 8, row = row0 + r;
    float ue_acc = 0.0f;
    FragC acc[4];

    for (int t = blockIdx.x; t < nTiles; t += gridDim.x) {
        size_t base = (size_t)t * 64;
        __syncthreads();  // prev-iter fstage/spart consumed; W loads visible

        // stage idx + ef -> A hi/lo
        if (tid < 64) {
            s_src[tid] = srcI[base + tid];
            s_dst[tid] = dstI[base + tid];
        }
        {
            int rr = tid >> 2, q = tid & 3;
            const float4* g4 = (const float4*)(ef + (base + rr) * 64 + q * 16);
#pragma unroll
            for (int qq = 0; qq < 4; qq++) {
                float4 v = __ldg(g4 + qq);
                int c = q * 16 + qq * 4;
                u32 hi, lo;
                split2(v.x, v.y, hi, lo);
                *(u32*)(smem + E_A_H + (rr * SA + c) * 2) = hi;
                *(u32*)(smem + E_A_L + (rr * SA + c) * 2) = lo;
                split2(v.z, v.w, hi, lo);
                *(u32*)(smem + E_A_H + (rr * SA + c + 2) * 2) = hi;
                *(u32*)(smem + E_A_L + (rr * SA + c + 2) * 2) = lo;
            }
        }
        __syncthreads();

        // ---- phase 0: pre-edge K=64 N=64 ----
        mma_half(smem, E_A_H, E_A_L, E_WP_H, E_WP_L, row0, 64, 72, h * 32, 2, acc);
        __syncthreads();
#pragma unroll
        for (int n = 0; n < 2; n++) {
            wmma::store_matrix_sync(stg, acc[n], 20, wmma::mem_row_major);
            __syncwarp();
            int col = h * 32 + n * 16 + c0;
            float v[8];
#pragma unroll
            for (int j = 0; j < 8; j++) v[j] = sp(stg[r * 20 + c0 + j] + s_pb[col + j]);
            store_A8(smem, E_A_H, E_A_L, row, col, v);
            __syncwarp();
        }
        __syncthreads();

        // ---- phase 1: L0 K=64 N=128 (+ As[src]+Ad[dst]+ce) ----
        mma_half(smem, E_A_H, E_A_L, E_W0_H, E_W0_L, row0, 64, 136, h * 64, 4, acc);
        __syncthreads();
        {
            const float4* as4 = (const float4*)g_As + (size_t)s_src[row] * 32;
            const float4* ad4 = (const float4*)g_Ad + (size_t)s_dst[row] * 32;
#pragma unroll
            for (int n = 0; n < 4; n++) {
                wmma::store_matrix_sync(stg, acc[n], 20, wmma::mem_row_major);
                __syncwarp();
                int col = h * 64 + n * 16 + c0;
                float4 a0 = __ldg(as4 + (col >> 2)), a1 = __ldg(as4 + (col >> 2) + 1);
                float4 d0 = __ldg(ad4 + (col >> 2)), d1 = __ldg(ad4 + (col >> 2) + 1);
                float ga[8] = {a0.x + d0.x, a0.y + d0.y, a0.z + d0.z, a0.w + d0.w,
                               a1.x + d1.x, a1.y + d1.y, a1.z + d1.z, a1.w + d1.w};
                float v[8];
#pragma unroll
                for (int j = 0; j < 8; j++)
                    v[j] = sp(stg[r * 20 + c0 + j] + ga[j] + s_ce[col + j]);
                store_A8(smem, E_A_H, E_A_L, row, col, v);
                __syncwarp();
            }
        }
        __syncthreads();

        // ---- phase 2: L1 K=128 N=128 ----
        mma_half(smem, E_A_H, E_A_L, E_W1_H, E_W1_L, row0, 128, 136, h * 64, 4, acc);
        __syncthreads();
#pragma unroll
        for (int n = 0; n < 4; n++) {
            wmma::store_matrix_sync(stg, acc[n], 20, wmma::mem_row_major);
            __syncwarp();
            int col = h * 64 + n * 16 + c0;
            float v[8];
#pragma unroll
            for (int j = 0; j < 8; j++) v[j] = sp(stg[r * 20 + c0 + j] + s_b1[col + j]);
            store_A8(smem, E_A_H, E_A_L, row, col, v);
            __syncwarp();
        }
        __syncthreads();

        // ---- phase 3: L2 K=128 N=64 ----
        mma_half(smem, E_A_H, E_A_L, E_W2_H, E_W2_L, row0, 128, 72, h * 32, 2, acc);
        __syncthreads();
        {
            int dnode = s_dst[row];
#pragma unroll
            for (int n = 0; n < 2; n++) {
                wmma::store_matrix_sync(stg, acc[n], 20, wmma::mem_row_major);
                __syncwarp();
                int col = h * 32 + n * 16 + c0;
                float v[8];
#pragma unroll
                for (int j = 0; j < 8; j++)
                    v[j] = sp(stg[r * 20 + c0 + j] + s_b2[col + j]);
                size_t gidx = (base + row) * 64 + col;
                float4 e0 = __ldg((const float4*)(ef + gidx));
                float4 e1 = __ldg((const float4*)(ef + gidx) + 1);
                float4 o0 = {v[0] + e0.x, v[1] + e0.y, v[2] + e0.z, v[3] + e0.w};
                float4 o1 = {v[4] + e1.x, v[5] + e1.y, v[6] + e1.z, v[7] + e1.w};
                *(float4*)(e_out + gidx) = o0;
                *((float4*)(e_out + gidx) + 1) = o1;
                float* vrow = &g_ve[(size_t)dnode * 64 + col];
#pragma unroll
                for (int j = 0; j < 8; j++) {
                    atomicAdd(vrow + j, v[j]);
                    fstage[row * 68 + col + j] = v[j];
                }
                if (n == 0 && h == 0 && (lane & 1) == 0)
                    atomicAdd(&g_cnt[dnode], 1.0f);
                __syncwarp();
            }
        }
        __syncthreads();

        // ue partial: 256 threads, 16 rows each
        {
            int col = tid & 63, q = tid >> 6;
            float s = 0.0f;
#pragma unroll
            for (int rr = q * 16; rr < q * 16 + 16; rr++) s += fstage[rr * 68 + col];
            spart[tid] = s;
        }
        __syncthreads();
        if (tid < 64)
            ue_acc += spart[tid] + spart[64 + tid] + spart[128 + tid] + spart[192 + tid];
    }
    if (tid < 64) atomicAdd(&g_ue[tid], ue_acc);
}

// ---------------------------------------------------------------------------
// persistent fused node kernel: 64 nodes / iteration
// ---------------------------------------------------------------------------
__global__ __launch_bounds__(256) void node_kernel(
    const float* __restrict__ nf, const float* __restrict__ b1,
    const float* __restrict__ b2, float* __restrict__ v_out, int nNodes,
    int nTiles) {
    extern __shared__ char smem[];
    int tid = threadIdx.x, wid = tid >> 5, lane = tid & 31;

    float* s_cn  = (float*)(smem + N_MISC);
    float* s_b1  = (float*)(smem + N_MISC + 512);
    float* s_b2  = (float*)(smem + N_MISC + 1024);
    float* spart = (float*)(smem + N_MISC + 1536);
    float* stg   = (float*)(smem + N_STG) + wid * 320;
    float* fstage = (float*)(smem + N_A_H);

    load_W_seg(smem, 36864, 128, 128, 136, N_W0_H, N_W0_L, tid);
    load_W_seg(smem, 53248, 128, 128, 136, N_W1_H, N_W1_L, tid);
    load_W_seg(smem, 69632, 128, 64,  72, N_W2_H, N_W2_L, tid);
    if (tid < 128) {
        s_cn[tid] = g_cn[tid];
        s_b1[tid] = __ldg(b1 + tid);
    } else if (tid >= 192) {
        s_b2[tid - 192] = __ldg(b2 + tid - 192);
    }

    int slab = wid & 3, h = wid >> 2, row0 = slab * 16;
    int r = lane >> 1, c0 = (lane & 1) * 8, row = row0 + r;
    float uv_acc = 0.0f;
    FragC acc[4];

    for (int t = blockIdx.x; t < nTiles; t += gridDim.x) {
        size_t base = (size_t)t * 64;
        __syncthreads();

        // stage X = [v_pre | ve_mean] -> A hi/lo (K=128)
        {
            int rr = tid & 63, hh = tid >> 6;  // hh: quarter 0..3, 32 cols each
            size_t gn = base + rr;
            if (gn >= (size_t)nNodes) gn = nNodes - 1;
            const float4* g4;
            float scale = 1.0f;
            if (hh < 2) {
                g4 = (const float4*)(g_v_pre + gn * 64) + hh * 8;
            } else {
                g4 = (const float4*)(g_ve + gn * 64) + (hh - 2) * 8;
                scale = 1.0f / fmaxf(g_cnt[gn], 1.0f);
            }
#pragma unroll
            for (int q = 0; q < 8; q++) {
                float4 v = __ldg(g4 + q);
                v.x *= scale; v.y *= scale; v.z *= scale; v.w *= scale;
                int c = hh * 32 + q * 4;
                u32 hi, lo;
                split2(v.x, v.y, hi, lo);
                *(u32*)(smem + N_A_H + (rr * SA + c) * 2) = hi;
                *(u32*)(smem + N_A_L + (rr * SA + c) * 2) = lo;
                split2(v.z, v.w, hi, lo);
                *(u32*)(smem + N_A_H + (rr * SA + c + 2) * 2) = hi;
                *(u32*)(smem + N_A_L + (rr * SA + c + 2) * 2) = lo;
            }
        }
        __syncthreads();

        bool valid = (base + row) < (size_t)nNodes;

        // ---- L0: K=128 N=128 (bias cn) ----
        mma_half(smem, N_A_H, N_A_L, N_W0_H, N_W0_L, row0, 128, 136, h * 64, 4, acc);
        __syncthreads();
#pragma unroll
        for (int n = 0; n < 4; n++) {
            wmma::store_matrix_sync(stg, acc[n], 20, wmma::mem_row_major);
            __syncwarp();
            int col = h * 64 + n * 16 + c0;
            float v[8];
#pragma unroll
            for (int j = 0; j < 8; j++) v[j] = sp(stg[r * 20 + c0 + j] + s_cn[col + j]);
            store_A8(smem, N_A_H, N_A_L, row, col, v);
            __syncwarp();
        }
        __syncthreads();

        // ---- L1: K=128 N=128 ----
        mma_half(smem, N_A_H, N_A_L, N_W1_H, N_W1_L, row0, 128, 136, h * 64, 4, acc);
        __syncthreads();
#pragma unroll
        for (int n = 0; n < 4; n++) {
            wmma::store_matrix_sync(stg, acc[n], 20, wmma::mem_row_major);
            __syncwarp();
            int col = h * 64 + n * 16 + c0;
            float v[8];
#pragma unroll
            for (int j = 0; j < 8; j++) v[j] = sp(stg[r * 20 + c0 + j] + s_b1[col + j]);
            store_A8(smem, N_A_H, N_A_L, row, col, v);
            __syncwarp();
        }
        __syncthreads();

        // ---- L2: K=128 N=64 ----
        mma_half(smem, N_A_H, N_A_L, N_W2_H, N_W2_L, row0, 128, 72, h * 32, 2, acc);
        __syncthreads();
#pragma unroll
        for (int n = 0; n < 2; n++) {
            wmma::store_matrix_sync(stg, acc[n], 20, wmma::mem_row_major);
            __syncwarp();
            int col = h * 32 + n * 16 + c0;
            float v[8];
#pragma unroll
            for (int j = 0; j < 8; j++) v[j] = sp(stg[r * 20 + c0 + j] + s_b2[col + j]);
            if (valid) {
                size_t gidx = (base + row) * 64 + col;
                float4 e0 = __ldg((const float4*)(nf + gidx));
                float4 e1 = __ldg((const float4*)(nf + gidx) + 1);
                float4 o0 = {v[0] + e0.x, v[1] + e0.y, v[2] + e0.z, v[3] + e0.w};
                float4 o1 = {v[4] + e1.x, v[5] + e1.y, v[6] + e1.z, v[7] + e1.w};
                *(float4*)(v_out + gidx) = o0;
                *((float4*)(v_out + gidx) + 1) = o1;
            }
#pragma unroll
            for (int j = 0; j < 8; j++)
                fstage[row * 68 + col + j] = valid ? v[j] : 0.0f;
            __syncwarp();
        }
        __syncthreads();

        {
            int col = tid & 63, q = tid >> 6;
            float s = 0.0f;
#pragma unroll
            for (int rr = q * 16; rr < q * 16 + 16; rr++) s += fstage[rr * 68 + col];
            spart[tid] = s;
        }
        __syncthreads();
        if (tid < 64)
            uv_acc += spart[tid] + spart[64 + tid] + spart[128 + tid] + spart[192 + tid];
    }
    if (tid < 64) atomicAdd(&g_uv[tid], uv_acc);
}

// ---------------------------------------------------------------------------
__global__ void attr_kernel(const float* __restrict__ ga,
                            const float* __restrict__ w0,
                            const float* __restrict__ b0,
                            const float* __restrict__ w1,
                            const float* __restrict__ b1,
                            const float* __restrict__ w2,
                            const float* __restrict__ b2,
                            float* __restrict__ out, float invE, float invN) {
    __shared__ float x[192], h0[128], h1[128];
    int t = threadIdx.x;
    if (t < 64) {
        x[t]       = g_u_pre[t];
        x[64 + t]  = g_ue[t] * invE;
        x[128 + t] = g_uv[t] * invN;
    }
    __syncthreads();
    float acc = b0[t];
    for (int k = 0; k < 192; k++) acc = fmaf(x[k], w0[k * 128 + t], acc);
    h0[t] = sp(acc);
    __syncthreads();
    acc = b1[t];
    for (int k = 0; k < 128; k++) acc = fmaf(h0[k], w1[k * 128 + t], acc);
    h1[t] = sp(acc);
    __syncthreads();
    if (t < 64) {
        float a = b2[t];
        for (int k = 0; k < 128; k++) a = fmaf(h1[k], w2[k * 64 + t], a);
        out[t] = sp(a) + ga[t];
    }
}

// ---------------------------------------------------------------------------
extern "C" void kernel_launch(void* const* d_in, const int* in_sizes, int n_in,
                              void* d_out, int out_size) {
    const float* edge_feat  = (const float*)d_in[0];
    const float* node_feat  = (const float*)d_in[1];
    const float* graph_attr = (const float*)d_in[2];
    const int*   src        = (const int*)d_in[3];
    const int*   dst        = (const int*)d_in[4];
    const float* pre_edge_w = (const float*)d_in[5];
    const float* pre_edge_b = (const float*)d_in[6];
    const float* pre_node_w = (const float*)d_in[7];
    const float* pre_node_b = (const float*)d_in[8];
    const float* pre_attr_w = (const float*)d_in[9];
    const float* pre_attr_b = (const float*)d_in[10];
    const float* edge_w0 = (const float*)d_in[11];
    const float* edge_b0 = (const float*)d_in[12];
    const float* edge_w1 = (const float*)d_in[13];
    const float* edge_b1 = (const float*)d_in[14];
    const float* edge_w2 = (const float*)d_in[15];
    const float* edge_b2 = (const float*)d_in[16];
    const float* node_w0 = (const float*)d_in[17];
    const float* node_b0 = (const float*)d_in[18];
    const float* node_w1 = (const float*)d_in[19];
    const float* node_b1 = (const float*)d_in[20];
    const float* node_w2 = (const float*)d_in[21];
    const float* node_b2 = (const float*)d_in[22];
    const float* attr_w0 = (const float*)d_in[23];
    const float* attr_b0 = (const float*)d_in[24];
    const float* attr_w1 = (const float*)d_in[25];
    const float* attr_b1 = (const float*)d_in[26];
    const float* attr_w2 = (const float*)d_in[27];
    const float* attr_b2 = (const float*)d_in[28];

    float* out = (float*)d_out;
    int E = in_sizes[3];
    int N = in_sizes[1] / 64;
    int eTiles = E / 64;
    int nTiles = (N + 63) / 64;

    cudaFuncSetAttribute(edge_kernel, cudaFuncAttributeMaxDynamicSharedMemorySize,
                         E_TOTAL);
    cudaFuncSetAttribute(node_kernel, cudaFuncAttributeMaxDynamicSharedMemorySize,
                         N_TOTAL);

    zero_kernel<<<256, 256>>>(N);
    pre_attr_kernel<<<1, 64>>>(graph_attr, pre_attr_w, pre_attr_b);
    const_kernel<<<1, 128>>>(edge_w0, edge_b0, node_w0, node_b0);
    prep_w_kernel<<<64, 256>>>(pre_edge_w, edge_w0, edge_w1, edge_w2, node_w0,
                               node_w1, node_w2);
    pre_nodeA_kernel<<<N / 32, 128>>>(node_feat, pre_node_w, pre_node_b, edge_w0);
    edge_kernel<<<NUM_CTAS, 256, E_TOTAL>>>(edge_feat, src, dst, pre_edge_b,
                                            edge_b1, edge_b2, out, eTiles);
    node_kernel<<<NUM_CTAS, 256, N_TOTAL>>>(node_feat, node_b1, node_b2,
                                            out + (size_t)E * 64, N, nTiles);
    attr_kernel<<<1, 128>>>(graph_attr, attr_w0, attr_b0, attr_w1, attr_b1,
                            attr_w2, attr_b2,
                            out + (size_t)E * 64 + (size_t)N * 64,
                            1.0f / (float)E, 1.0f / (float)N);
}

// round 8
// speedup vs baseline: 2.4545x; 1.1494x over previous
#include <cuda_runtime.h>
#include <cuda_bf16.h>
#include <mma.h>
#include <cstdint>
#include <cstddef>

using namespace nvcuda;

// ---------------------------------------------------------------------------
// MegNetBlock — persistent wmma bf16 (hi/lo 3-pass), weights resident in smem
// 512-thread edge kernel + fast softplus
// N=100000, E=800000, D=64, H=128
// ---------------------------------------------------------------------------

#define NMAX 100000
typedef unsigned int u32;

// ---------------- scratch (device globals) ----------------
__device__ float  g_v_pre[NMAX * 64];
__device__ float4 g_As[NMAX * 32];
__device__ float4 g_Ad[NMAX * 32];
__device__ float  g_ve[NMAX * 64];
__device__ float  g_cnt[NMAX];
__device__ float  g_u_pre[64];
__device__ __align__(16) float g_ce[128];
__device__ __align__(16) float g_cn[128];
__device__ float  g_ue[64];
__device__ float  g_uv[64];

// bf16 hi/lo split weights, [k][n] row-major per segment
__device__ __align__(16) __nv_bfloat16 g_W_h[77824];
__device__ __align__(16) __nv_bfloat16 g_W_l[77824];

// ---------------- smem layouts (byte offsets) ----------------
static constexpr int SA = 136;   // A row stride in bf16 elems

// edge kernel (512 threads, 16 warps)
static constexpr int E_WP_H = 0;        // 64x72
static constexpr int E_WP_L = 9216;
static constexpr int E_W0_H = 18432;    // 64x136
static constexpr int E_W0_L = 35840;
static constexpr int E_W1_H = 53248;    // 128x136
static constexpr int E_W1_L = 88064;
static constexpr int E_W2_H = 122880;   // 128x72
static constexpr int E_W2_L = 141312;
static constexpr int E_A_H  = 159744;   // 64x136
static constexpr int E_A_L  = 177152;
static constexpr int E_STG  = 194560;   // 16 warps x 16x20 f32 = 20480
static constexpr int E_MISC = 215040;   // src|dst|pb|b1|b2|ce|spart(512)
static constexpr int E_TOTAL = 219136;

// node kernel (256 threads, 8 warps)
static constexpr int N_W0_H = 0;
static constexpr int N_W0_L = 34816;
static constexpr int N_W1_H = 69632;
static constexpr int N_W1_L = 104448;
static constexpr int N_W2_H = 139264;
static constexpr int N_W2_L = 157696;
static constexpr int N_A_H  = 176128;
static constexpr int N_A_L  = 193536;
static constexpr int N_STG  = 210944;
static constexpr int N_MISC = 221184;
static constexpr int N_TOTAL = 223744;

static constexpr int NUM_CTAS = 148;

// ---------------- helpers ----------------
__device__ __forceinline__ float sp(float x) {
    // fast softplus: max(x,0) + log(1 + exp(-|x|)); abs err ~1e-7
    return fmaxf(x, 0.0f) + __logf(1.0f + __expf(-fabsf(x)));
}
__device__ __forceinline__ void split2(float v0, float v1, u32& hi, u32& lo) {
    __nv_bfloat16 h0 = __float2bfloat16(v0), h1 = __float2bfloat16(v1);
    float f0 = __bfloat162float(h0), f1 = __bfloat162float(h1);
    __nv_bfloat16 l0 = __float2bfloat16(v0 - f0), l1 = __float2bfloat16(v1 - f1);
    hi = ((u32)__bfloat16_as_ushort(h1) << 16) | __bfloat16_as_ushort(h0);
    lo = ((u32)__bfloat16_as_ushort(l1) << 16) | __bfloat16_as_ushort(l0);
}

typedef wmma::fragment<wmma::matrix_a, 16, 16, 16, __nv_bfloat16, wmma::row_major> FragA;
typedef wmma::fragment<wmma::matrix_b, 16, 16, 16, __nv_bfloat16, wmma::row_major> FragB;
typedef wmma::fragment<wmma::accumulator, 16, 16, 16, float> FragC;

__device__ __forceinline__ void mma_half(const char* smem, int offAh, int offAl,
                                         int offWh, int offWl, int row0, int K,
                                         int SW, int colbase, int nt, FragC* acc) {
    const __nv_bfloat16* Ah = (const __nv_bfloat16*)(smem + offAh) + row0 * SA;
    const __nv_bfloat16* Al = (const __nv_bfloat16*)(smem + offAl) + row0 * SA;
    const __nv_bfloat16* Wh = (const __nv_bfloat16*)(smem + offWh) + colbase;
    const __nv_bfloat16* Wl = (const __nv_bfloat16*)(smem + offWl) + colbase;
    for (int n = 0; n < nt; n++) wmma::fill_fragment(acc[n], 0.0f);
    for (int k = 0; k < K; k += 16) {
        FragA ah, al;
        wmma::load_matrix_sync(ah, Ah + k, SA);
        wmma::load_matrix_sync(al, Al + k, SA);
        for (int n = 0; n < nt; n++) {
            FragB bh, bl;
            wmma::load_matrix_sync(bh, Wh + k * SW + n * 16, SW);
            wmma::load_matrix_sync(bl, Wl + k * SW + n * 16, SW);
            wmma::mma_sync(acc[n], ah, bh, acc[n]);
            wmma::mma_sync(acc[n], ah, bl, acc[n]);
            wmma::mma_sync(acc[n], al, bh, acc[n]);
        }
    }
}

__device__ __forceinline__ void load_W_seg(char* smem, int goff, int K, int N, int SW,
                                           int offh, int offl, int tid, int nthr) {
    const u32* gh = (const u32*)(g_W_h + goff);
    const u32* gl = (const u32*)(g_W_l + goff);
    int total2 = K * N / 2;
    for (int i2 = tid; i2 < total2; i2 += nthr) {
        int k = (2 * i2) / N, n = (2 * i2) % N;
        int d = (k * SW + n) * 2;
        *(u32*)(smem + offh + d) = gh[i2];
        *(u32*)(smem + offl + d) = gl[i2];
    }
}

__device__ __forceinline__ void store_A8(char* smem, int offAh, int offAl, int row,
                                         int col, const float* v) {
#pragma unroll
    for (int j = 0; j < 8; j += 2) {
        u32 hi, lo;
        split2(v[j], v[j + 1], hi, lo);
        int d = (row * SA + col + j) * 2;
        *(u32*)(smem + offAh + d) = hi;
        *(u32*)(smem + offAl + d) = lo;
    }
}

// ---------------------------------------------------------------------------
__global__ void zero_kernel(int nNodes) {
    int total = nNodes * 64 + nNodes + 128;
    for (int i = blockIdx.x * blockDim.x + threadIdx.x; i < total;
         i += gridDim.x * blockDim.x) {
        if (i < nNodes * 64) g_ve[i] = 0.0f;
        else if (i < nNodes * 64 + nNodes) g_cnt[i - nNodes * 64] = 0.0f;
        else {
            int j = i - nNodes * 64 - nNodes;
            if (j < 64) g_ue[j] = 0.0f; else g_uv[j - 64] = 0.0f;
        }
    }
}

__global__ void pre_attr_kernel(const float* __restrict__ ga,
                                const float* __restrict__ w,
                                const float* __restrict__ b) {
    __shared__ float sg[64];
    int t = threadIdx.x;
    sg[t] = ga[t];
    __syncthreads();
    float acc = b[t];
    for (int k = 0; k < 64; k++) acc = fmaf(sg[k], w[k * 64 + t], acc);
    g_u_pre[t] = sp(acc);
}

__global__ void const_kernel(const float* __restrict__ ew0,
                             const float* __restrict__ eb0,
                             const float* __restrict__ nw0,
                             const float* __restrict__ nb0) {
    __shared__ float su[64];
    int t = threadIdx.x;  // 128
    if (t < 64) su[t] = g_u_pre[t];
    __syncthreads();
    float a = eb0[t], c = nb0[t];
    for (int k = 0; k < 64; k++) {
        a = fmaf(su[k], ew0[(192 + k) * 128 + t], a);
        c = fmaf(su[k], nw0[(128 + k) * 128 + t], c);
    }
    g_ce[t] = a;
    g_cn[t] = c;
}

__global__ void prep_w_kernel(const float* pw, const float* ew0,
                              const float* ew1, const float* ew2,
                              const float* nw0, const float* nw1,
                              const float* nw2) {
    const float* srcs[7] = {pw, ew0 + 128 * 128, ew1, ew2, nw0, nw1, nw2};
    const int KN[7] = {4096, 8192, 16384, 8192, 16384, 16384, 8192};
    const int off[7] = {0, 4096, 12288, 28672, 36864, 53248, 69632};
#pragma unroll 1
    for (int s = 0; s < 7; s++) {
        const float* sc = srcs[s];
        for (int i = blockIdx.x * blockDim.x + threadIdx.x; i < KN[s];
             i += gridDim.x * blockDim.x) {
            float v = sc[i];
            __nv_bfloat16 h = __float2bfloat16(v);
            g_W_h[off[s] + i] = h;
            g_W_l[off[s] + i] = __float2bfloat16(v - __bfloat162float(h));
        }
    }
}

// ---------------------------------------------------------------------------
__global__ __launch_bounds__(128) void pre_nodeA_kernel(
    const float* __restrict__ nf, const float* __restrict__ pw,
    const float* __restrict__ pb, const float* __restrict__ ew0) {
    __shared__ float snf[2048];
    __shared__ float sv[2048];
    int tid = threadIdx.x;
    size_t base = (size_t)blockIdx.x * 32;

    for (int i = tid; i < 512; i += 128)
        ((float4*)snf)[i] = ((const float4*)(nf + base * 64))[i];
    __syncthreads();

    {
        int col = tid & 63, hf = tid >> 6;
        float bb = pb[col];
        float acc[16];
#pragma unroll
        for (int i = 0; i < 16; i++) acc[i] = bb;
        const float* xr = snf + hf * 16 * 64;
        for (int k = 0; k < 64; k += 4) {
            float wa = __ldg(pw + k * 64 + col), wb = __ldg(pw + (k + 1) * 64 + col);
            float wc = __ldg(pw + (k + 2) * 64 + col), wd = __ldg(pw + (k + 3) * 64 + col);
#pragma unroll
            for (int i = 0; i < 16; i++) {
                float4 xv = *(const float4*)(xr + i * 64 + k);
                acc[i] = fmaf(xv.x, wa, acc[i]);
                acc[i] = fmaf(xv.y, wb, acc[i]);
                acc[i] = fmaf(xv.z, wc, acc[i]);
                acc[i] = fmaf(xv.w, wd, acc[i]);
            }
        }
#pragma unroll
        for (int i = 0; i < 16; i++) {
            float v = sp(acc[i]);
            sv[(hf * 16 + i) * 64 + col] = v;
            g_v_pre[(base + hf * 16 + i) * 64 + col] = v;
        }
    }
    __syncthreads();

    float* Asf = (float*)g_As;
    float* Adf = (float*)g_Ad;
    int j = tid;
#pragma unroll 1
    for (int m = 0; m < 2; m++) {
        const float* w = ew0 + (size_t)m * 64 * 128;
        float acc[32];
#pragma unroll
        for (int e = 0; e < 32; e++) acc[e] = 0.0f;
        for (int k = 0; k < 64; k += 4) {
            float wa = __ldg(w + k * 128 + j), wb = __ldg(w + (k + 1) * 128 + j);
            float wc = __ldg(w + (k + 2) * 128 + j), wd = __ldg(w + (k + 3) * 128 + j);
#pragma unroll
            for (int e = 0; e < 32; e++) {
                float4 xv = *(const float4*)(sv + e * 64 + k);
                acc[e] = fmaf(xv.x, wa, acc[e]);
                acc[e] = fmaf(xv.y, wb, acc[e]);
                acc[e] = fmaf(xv.z, wc, acc[e]);
                acc[e] = fmaf(xv.w, wd, acc[e]);
            }
        }
        float* dstp = m ? Adf : Asf;
#pragma unroll
        for (int e = 0; e < 32; e++) dstp[(base + e) * 128 + j] = acc[e];
    }
}

// ---------------------------------------------------------------------------
// persistent fused edge kernel: 64 edges / iteration, 512 threads / 16 warps
// warp (slab, h): rows slab*16..+16, cols h*(N/4)..
// ---------------------------------------------------------------------------
__global__ __launch_bounds__(512) void edge_kernel(
    const float* __restrict__ ef, const int* __restrict__ srcI,
    const int* __restrict__ dstI, const float* __restrict__ pb,
    const float* __restrict__ b1, const float* __restrict__ b2,
    float* __restrict__ e_out, int nTiles) {
    extern __shared__ char smem[];
    int tid = threadIdx.x, wid = tid >> 5, lane = tid & 31;

    int*   s_src = (int*)(smem + E_MISC);
    int*   s_dst = (int*)(smem + E_MISC + 256);
    float* s_pb  = (float*)(smem + E_MISC + 512);
    float* s_b1  = (float*)(smem + E_MISC + 768);
    float* s_b2  = (float*)(smem + E_MISC + 1280);
    float* s_ce  = (float*)(smem + E_MISC + 1536);
    float* spart = (float*)(smem + E_MISC + 2048);
    float* stg   = (float*)(smem + E_STG) + wid * 320;
    float* fstage = (float*)(smem + E_A_H);  // f32 [64][68]

    load_W_seg(smem, 0,     64, 64,  72, E_WP_H, E_WP_L, tid, 512);
    load_W_seg(smem, 4096,  64, 128, 136, E_W0_H, E_W0_L, tid, 512);
    load_W_seg(smem, 12288, 128, 128, 136, E_W1_H, E_W1_L, tid, 512);
    load_W_seg(smem, 28672, 128, 64,  72, E_W2_H, E_W2_L, tid, 512);
    if (tid < 128) {
        s_ce[tid] = g_ce[tid];
        s_b1[tid] = __ldg(b1 + tid);
    } else if (tid < 192) {
        s_pb[tid - 128] = __ldg(pb + tid - 128);
    } else if (tid < 256) {
        s_b2[tid - 192] = __ldg(b2 + tid - 192);
    }

    int slab = wid & 3, h = wid >> 2, row0 = slab * 16;
    int r = lane >> 1, c0 = (lane & 1) * 8, row = row0 + r;
    float ue_acc = 0.0f;
    FragC acc[2];

    for (int t = blockIdx.x; t < nTiles; t += gridDim.x) {
        size_t base = (size_t)t * 64;
        __syncthreads();

        if (tid < 64) {
            s_src[tid] = srcI[base + tid];
            s_dst[tid] = dstI[base + tid];
        }
        // stage ef -> A hi/lo: 1024 float4s
        for (int i = tid; i < 1024; i += 512) {
            int rr = i >> 4, q = i & 15;
            float4 v = __ldg((const float4*)(ef + (base + rr) * 64) + q);
            int c = q * 4;
            u32 hi, lo;
            split2(v.x, v.y, hi, lo);
            *(u32*)(smem + E_A_H + (rr * SA + c) * 2) = hi;
            *(u32*)(smem + E_A_L + (rr * SA + c) * 2) = lo;
            split2(v.z, v.w, hi, lo);
            *(u32*)(smem + E_A_H + (rr * SA + c + 2) * 2) = hi;
            *(u32*)(smem + E_A_L + (rr * SA + c + 2) * 2) = lo;
        }
        __syncthreads();

        // ---- phase 0: pre-edge K=64 N=64 ----
        mma_half(smem, E_A_H, E_A_L, E_WP_H, E_WP_L, row0, 64, 72, h * 16, 1, acc);
        __syncthreads();
        {
            wmma::store_matrix_sync(stg, acc[0], 20, wmma::mem_row_major);
            __syncwarp();
            int col = h * 16 + c0;
            float v[8];
#pragma unroll
            for (int j = 0; j < 8; j++) v[j] = sp(stg[r * 20 + c0 + j] + s_pb[col + j]);
            store_A8(smem, E_A_H, E_A_L, row, col, v);
        }
        __syncthreads();

        // ---- phase 1: L0 K=64 N=128 (+ As[src]+Ad[dst]+ce) ----
        mma_half(smem, E_A_H, E_A_L, E_W0_H, E_W0_L, row0, 64, 136, h * 32, 2, acc);
        __syncthreads();
        {
            const float4* as4 = (const float4*)g_As + (size_t)s_src[row] * 32;
            const float4* ad4 = (const float4*)g_Ad + (size_t)s_dst[row] * 32;
#pragma unroll
            for (int n = 0; n < 2; n++) {
                wmma::store_matrix_sync(stg, acc[n], 20, wmma::mem_row_major);
                __syncwarp();
                int col = h * 32 + n * 16 + c0;
                float4 a0 = __ldg(as4 + (col >> 2)), a1 = __ldg(as4 + (col >> 2) + 1);
                float4 d0 = __ldg(ad4 + (col >> 2)), d1 = __ldg(ad4 + (col >> 2) + 1);
                float ga[8] = {a0.x + d0.x, a0.y + d0.y, a0.z + d0.z, a0.w + d0.w,
                               a1.x + d1.x, a1.y + d1.y, a1.z + d1.z, a1.w + d1.w};
                float v[8];
#pragma unroll
                for (int j = 0; j < 8; j++)
                    v[j] = sp(stg[r * 20 + c0 + j] + ga[j] + s_ce[col + j]);
                store_A8(smem, E_A_H, E_A_L, row, col, v);
                __syncwarp();
            }
        }
        __syncthreads();

        // ---- phase 2: L1 K=128 N=128 ----
        mma_half(smem, E_A_H, E_A_L, E_W1_H, E_W1_L, row0, 128, 136, h * 32, 2, acc);
        __syncthreads();
#pragma unroll
        for (int n = 0; n < 2; n++) {
            wmma::store_matrix_sync(stg, acc[n], 20, wmma::mem_row_major);
            __syncwarp();
            int col = h * 32 + n * 16 + c0;
            float v[8];
#pragma unroll
            for (int j = 0; j < 8; j++) v[j] = sp(stg[r * 20 + c0 + j] + s_b1[col + j]);
            store_A8(smem, E_A_H, E_A_L, row, col, v);
            __syncwarp();
        }
        __syncthreads();

        // ---- phase 3: L2 K=128 N=64 ----
        mma_half(smem, E_A_H, E_A_L, E_W2_H, E_W2_L, row0, 128, 72, h * 16, 1, acc);
        __syncthreads();
        {
            int dnode = s_dst[row];
            wmma::store_matrix_sync(stg, acc[0], 20, wmma::mem_row_major);
            __syncwarp();
            int col = h * 16 + c0;
            float v[8];
#pragma unroll
            for (int j = 0; j < 8; j++) v[j] = sp(stg[r * 20 + c0 + j] + s_b2[col + j]);
            size_t gidx = (base + row) * 64 + col;
            float4 e0 = __ldg((const float4*)(ef + gidx));
            float4 e1 = __ldg((const float4*)(ef + gidx) + 1);
            float4 o0 = {v[0] + e0.x, v[1] + e0.y, v[2] + e0.z, v[3] + e0.w};
            float4 o1 = {v[4] + e1.x, v[5] + e1.y, v[6] + e1.z, v[7] + e1.w};
            *(float4*)(e_out + gidx) = o0;
            *((float4*)(e_out + gidx) + 1) = o1;
            float* vrow = &g_ve[(size_t)dnode * 64 + col];
#pragma unroll
            for (int j = 0; j < 8; j++) {
                atomicAdd(vrow + j, v[j]);
                fstage[row * 68 + col + j] = v[j];
            }
            if (h == 0 && (lane & 1) == 0) atomicAdd(&g_cnt[dnode], 1.0f);
        }
        __syncthreads();

        // ue partial: 512 threads, 8 rows each
        {
            int col = tid & 63, q = tid >> 6;
            float s = 0.0f;
#pragma unroll
            for (int rr = q * 8; rr < q * 8 + 8; rr++) s += fstage[rr * 68 + col];
            spart[tid] = s;
        }
        __syncthreads();
        if (tid < 64) {
            float s = 0.0f;
#pragma unroll
            for (int q = 0; q < 8; q++) s += spart[q * 64 + tid];
            ue_acc += s;
        }
    }
    if (tid < 64) atomicAdd(&g_ue[tid], ue_acc);
}

// ---------------------------------------------------------------------------
// persistent fused node kernel: 64 nodes / iteration, 256 threads
// ---------------------------------------------------------------------------
__global__ __launch_bounds__(256) void node_kernel(
    const float* __restrict__ nf, const float* __restrict__ b1,
    const float* __restrict__ b2, float* __restrict__ v_out, int nNodes,
    int nTiles) {
    extern __shared__ char smem[];
    int tid = threadIdx.x, wid = tid >> 5, lane = tid & 31;

    float* s_cn  = (float*)(smem + N_MISC);
    float* s_b1  = (float*)(smem + N_MISC + 512);
    float* s_b2  = (float*)(smem + N_MISC + 1024);
    float* spart = (float*)(smem + N_MISC + 1536);
    float* stg   = (float*)(smem + N_STG) + wid * 320;
    float* fstage = (float*)(smem + N_A_H);

    load_W_seg(smem, 36864, 128, 128, 136, N_W0_H, N_W0_L, tid, 256);
    load_W_seg(smem, 53248, 128, 128, 136, N_W1_H, N_W1_L, tid, 256);
    load_W_seg(smem, 69632, 128, 64,  72, N_W2_H, N_W2_L, tid, 256);
    if (tid < 128) {
        s_cn[tid] = g_cn[tid];
        s_b1[tid] = __ldg(b1 + tid);
    } else if (tid >= 192) {
        s_b2[tid - 192] = __ldg(b2 + tid - 192);
    }

    int slab = wid & 3, h = wid >> 2, row0 = slab * 16;
    int r = lane >> 1, c0 = (lane & 1) * 8, row = row0 + r;
    float uv_acc = 0.0f;
    FragC acc[4];

    for (int t = blockIdx.x; t < nTiles; t += gridDim.x) {
        size_t base = (size_t)t * 64;
        __syncthreads();

        {
            int rr = tid & 63, hh = tid >> 6;
            size_t gn = base + rr;
            if (gn >= (size_t)nNodes) gn = nNodes - 1;
            const float4* g4;
            float scale = 1.0f;
            if (hh < 2) {
                g4 = (const float4*)(g_v_pre + gn * 64) + hh * 8;
            } else {
                g4 = (const float4*)(g_ve + gn * 64) + (hh - 2) * 8;
                scale = 1.0f / fmaxf(g_cnt[gn], 1.0f);
            }
#pragma unroll
            for (int q = 0; q < 8; q++) {
                float4 v = __ldg(g4 + q);
                v.x *= scale; v.y *= scale; v.z *= scale; v.w *= scale;
                int c = hh * 32 + q * 4;
                u32 hi, lo;
                split2(v.x, v.y, hi, lo);
                *(u32*)(smem + N_A_H + (rr * SA + c) * 2) = hi;
                *(u32*)(smem + N_A_L + (rr * SA + c) * 2) = lo;
                split2(v.z, v.w, hi, lo);
                *(u32*)(smem + N_A_H + (rr * SA + c + 2) * 2) = hi;
                *(u32*)(smem + N_A_L + (rr * SA + c + 2) * 2) = lo;
            }
        }
        __syncthreads();

        bool valid = (base + row) < (size_t)nNodes;

        // ---- L0: K=128 N=128 ----
        mma_half(smem, N_A_H, N_A_L, N_W0_H, N_W0_L, row0, 128, 136, h * 64, 4, acc);
        __syncthreads();
#pragma unroll
        for (int n = 0; n < 4; n++) {
            wmma::store_matrix_sync(stg, acc[n], 20, wmma::mem_row_major);
            __syncwarp();
            int col = h * 64 + n * 16 + c0;
            float v[8];
#pragma unroll
            for (int j = 0; j < 8; j++) v[j] = sp(stg[r * 20 + c0 + j] + s_cn[col + j]);
            store_A8(smem, N_A_H, N_A_L, row, col, v);
            __syncwarp();
        }
        __syncthreads();

        // ---- L1: K=128 N=128 ----
        mma_half(smem, N_A_H, N_A_L, N_W1_H, N_W1_L, row0, 128, 136, h * 64, 4, acc);
        __syncthreads();
#pragma unroll
        for (int n = 0; n < 4; n++) {
            wmma::store_matrix_sync(stg, acc[n], 20, wmma::mem_row_major);
            __syncwarp();
            int col = h * 64 + n * 16 + c0;
            float v[8];
#pragma unroll
            for (int j = 0; j < 8; j++) v[j] = sp(stg[r * 20 + c0 + j] + s_b1[col + j]);
            store_A8(smem, N_A_H, N_A_L, row, col, v);
            __syncwarp();
        }
        __syncthreads();

        // ---- L2: K=128 N=64 ----
        mma_half(smem, N_A_H, N_A_L, N_W2_H, N_W2_L, row0, 128, 72, h * 32, 2, acc);
        __syncthreads();
#pragma unroll
        for (int n = 0; n < 2; n++) {
            wmma::store_matrix_sync(stg, acc[n], 20, wmma::mem_row_major);
            __syncwarp();
            int col = h * 32 + n * 16 + c0;
            float v[8];
#pragma unroll
            for (int j = 0; j < 8; j++) v[j] = sp(stg[r * 20 + c0 + j] + s_b2[col + j]);
            if (valid) {
                size_t gidx = (base + row) * 64 + col;
                float4 e0 = __ldg((const float4*)(nf + gidx));
                float4 e1 = __ldg((const float4*)(nf + gidx) + 1);
                float4 o0 = {v[0] + e0.x, v[1] + e0.y, v[2] + e0.z, v[3] + e0.w};
                float4 o1 = {v[4] + e1.x, v[5] + e1.y, v[6] + e1.z, v[7] + e1.w};
                *(float4*)(v_out + gidx) = o0;
                *((float4*)(v_out + gidx) + 1) = o1;
            }
#pragma unroll
            for (int j = 0; j < 8; j++)
                fstage[row * 68 + col + j] = valid ? v[j] : 0.0f;
            __syncwarp();
        }
        __syncthreads();

        {
            int col = tid & 63, q = tid >> 6;
            float s = 0.0f;
#pragma unroll
            for (int rr = q * 16; rr < q * 16 + 16; rr++) s += fstage[rr * 68 + col];
            spart[tid] = s;
        }
        __syncthreads();
        if (tid < 64)
            uv_acc += spart[tid] + spart[64 + tid] + spart[128 + tid] + spart[192 + tid];
    }
    if (tid < 64) atomicAdd(&g_uv[tid], uv_acc);
}

// ---------------------------------------------------------------------------
__global__ void attr_kernel(const float* __restrict__ ga,
                            const float* __restrict__ w0,
                            const float* __restrict__ b0,
                            const float* __restrict__ w1,
                            const float* __restrict__ b1,
                            const float* __restrict__ w2,
                            const float* __restrict__ b2,
                            float* __restrict__ out, float invE, float invN) {
    __shared__ float x[192], h0[128], h1[128];
    int t = threadIdx.x;
    if (t < 64) {
        x[t]       = g_u_pre[t];
        x[64 + t]  = g_ue[t] * invE;
        x[128 + t] = g_uv[t] * invN;
    }
    __syncthreads();
    float acc = b0[t];
    for (int k = 0; k < 192; k++) acc = fmaf(x[k], w0[k * 128 + t], acc);
    h0[t] = sp(acc);
    __syncthreads();
    acc = b1[t];
    for (int k = 0; k < 128; k++) acc = fmaf(h0[k], w1[k * 128 + t], acc);
    h1[t] = sp(acc);
    __syncthreads();
    if (t < 64) {
        float a = b2[t];
        for (int k = 0; k < 128; k++) a = fmaf(h1[k], w2[k * 64 + t], a);
        out[t] = sp(a) + ga[t];
    }
}

// ---------------------------------------------------------------------------
extern "C" void kernel_launch(void* const* d_in, const int* in_sizes, int n_in,
                              void* d_out, int out_size) {
    const float* edge_feat  = (const float*)d_in[0];
    const float* node_feat  = (const float*)d_in[1];
    const float* graph_attr = (const float*)d_in[2];
    const int*   src        = (const int*)d_in[3];
    const int*   dst        = (const int*)d_in[4];
    const float* pre_edge_w = (const float*)d_in[5];
    const float* pre_edge_b = (const float*)d_in[6];
    const float* pre_node_w = (const float*)d_in[7];
    const float* pre_node_b = (const float*)d_in[8];
    const float* pre_attr_w = (const float*)d_in[9];
    const float* pre_attr_b = (const float*)d_in[10];
    const float* edge_w0 = (const float*)d_in[11];
    const float* edge_b0 = (const float*)d_in[12];
    const float* edge_w1 = (const float*)d_in[13];
    const float* edge_b1 = (const float*)d_in[14];
    const float* edge_w2 = (const float*)d_in[15];
    const float* edge_b2 = (const float*)d_in[16];
    const float* node_w0 = (const float*)d_in[17];
    const float* node_b0 = (const float*)d_in[18];
    const float* node_w1 = (const float*)d_in[19];
    const float* node_b1 = (const float*)d_in[20];
    const float* node_w2 = (const float*)d_in[21];
    const float* node_b2 = (const float*)d_in[22];
    const float* attr_w0 = (const float*)d_in[23];
    const float* attr_b0 = (const float*)d_in[24];
    const float* attr_w1 = (const float*)d_in[25];
    const float* attr_b1 = (const float*)d_in[26];
    const float* attr_w2 = (const float*)d_in[27];
    const float* attr_b2 = (const float*)d_in[28];

    float* out = (float*)d_out;
    int E = in_sizes[3];
    int N = in_sizes[1] / 64;
    int eTiles = E / 64;
    int nTiles = (N + 63) / 64;

    cudaFuncSetAttribute(edge_kernel, cudaFuncAttributeMaxDynamicSharedMemorySize,
                         E_TOTAL);
    cudaFuncSetAttribute(node_kernel, cudaFuncAttributeMaxDynamicSharedMemorySize,
                         N_TOTAL);

    zero_kernel<<<256, 256>>>(N);
    pre_attr_kernel<<<1, 64>>>(graph_attr, pre_attr_w, pre_attr_b);
    const_kernel<<<1, 128>>>(edge_w0, edge_b0, node_w0, node_b0);
    prep_w_kernel<<<64, 256>>>(pre_edge_w, edge_w0, edge_w1, edge_w2, node_w0,
                               node_w1, node_w2);
    pre_nodeA_kernel<<<N / 32, 128>>>(node_feat, pre_node_w, pre_node_b, edge_w0);
    edge_kernel<<<NUM_CTAS, 512, E_TOTAL>>>(edge_feat, src, dst, pre_edge_b,
                                            edge_b1, edge_b2, out, eTiles);
    node_kernel<<<NUM_CTAS, 256, N_TOTAL>>>(node_feat, node_b1, node_b2,
                                            out + (size_t)E * 64, N, nTiles);
    attr_kernel<<<1, 128>>>(graph_attr, attr_w0, attr_b0, attr_w1, attr_b1,
                            attr_w2, attr_b2,
                            out + (size_t)E * 64 + (size_t)N * 64,
                            1.0f / (float)E, 1.0f / (float)N);
}

// round 9
// speedup vs baseline: 3.8026x; 1.5492x over previous
#include <cuda_runtime.h>
#include <cuda_fp16.h>
#include <mma.h>
#include <cstdint>
#include <cstddef>

using namespace nvcuda;

// ---------------------------------------------------------------------------
// MegNetBlock — persistent wmma fp16 (A hi/lo 2-pass, exact-fp16 weights)
// 128-row tiles, weights resident in smem.  N=100000, E=800000, D=64, H=128
// ---------------------------------------------------------------------------

#define NMAX 100000
typedef unsigned int u32;

// ---------------- scratch (device globals) ----------------
__device__ float  g_v_pre[NMAX * 64];
__device__ float4 g_As[NMAX * 32];
__device__ float4 g_Ad[NMAX * 32];
__device__ float  g_ve[NMAX * 64];
__device__ float  g_cnt[NMAX];
__device__ float  g_u_pre[64];
__device__ __align__(16) float g_ce[128];
__device__ __align__(16) float g_cn[128];
__device__ float  g_ue[64];
__device__ float  g_uv[64];

// fp16 weights, [k][n] row-major per segment (offsets in elems)
//  0 Wp 0 (64x64) | 1 W0e 4096 (64x128) | 2 W1e 12288 (128x128)
//  3 W2e 28672 (128x64) | 4 W0n 36864 | 5 W1n 53248 | 6 W2n 69632
__device__ __align__(16) __half g_W[77824];

// ---------------- smem layouts (byte offsets) ----------------
static constexpr int SA = 136;   // A row stride in fp16 elems

// edge kernel (512 threads, 16 warps, 128 rows/iter)
static constexpr int E_WP  = 0;        // 64x72   = 9216
static constexpr int E_W0  = 9216;     // 64x136  = 17408
static constexpr int E_W1  = 26624;    // 128x136 = 34816
static constexpr int E_W2  = 61440;    // 128x72  = 18432
static constexpr int E_A_H = 79872;    // 128x136 = 34816
static constexpr int E_A_L = 114688;   // 34816
static constexpr int E_STG = 149504;   // 16 x 16x20 f32 = 20480
static constexpr int E_MISC = 169984;  // src 512|dst 512|pb 256|b1 512|b2 256|ce 512|spart 2048
static constexpr int E_TOTAL = 174592;

// node kernel (512 threads, 128 rows/iter)
static constexpr int N_W0  = 0;        // 34816
static constexpr int N_W1  = 34816;    // 34816
static constexpr int N_W2  = 69632;    // 18432
static constexpr int N_A_H = 88064;    // 34816
static constexpr int N_A_L = 122880;   // 34816
static constexpr int N_STG = 157696;   // 20480
static constexpr int N_MISC = 178176;  // cn 512|b1 512|b2 256|spart 2048
static constexpr int N_TOTAL = 181504;

static constexpr int NUM_CTAS = 148;

// ---------------- helpers ----------------
__device__ __forceinline__ float sp(float x) {
    return fmaxf(x, 0.0f) + __logf(1.0f + __expf(-fabsf(x)));
}
// split two fp32 into packed fp16 hi-pair / lo-pair
__device__ __forceinline__ void split2(float v0, float v1, u32& hi, u32& lo) {
    __half h0 = __float2half_rn(v0), h1 = __float2half_rn(v1);
    __half l0 = __float2half_rn(v0 - __half2float(h0));
    __half l1 = __float2half_rn(v1 - __half2float(h1));
    hi = ((u32)__half_as_ushort(h1) << 16) | __half_as_ushort(h0);
    lo = ((u32)__half_as_ushort(l1) << 16) | __half_as_ushort(l0);
}

typedef wmma::fragment<wmma::matrix_a, 16, 16, 16, __half, wmma::row_major> FragA;
typedef wmma::fragment<wmma::matrix_b, 16, 16, 16, __half, wmma::row_major> FragB;
typedef wmma::fragment<wmma::accumulator, 16, 16, 16, float> FragC;

// C[row0:16, colbase..] = (A_hi + A_lo)[row0:, :K] @ W[:K, cols]  (2-pass)
__device__ __forceinline__ void mma_half(const char* smem, int offAh, int offAl,
                                         int offW, int row0, int K, int SW,
                                         int colbase, int nt, FragC* acc) {
    const __half* Ah = (const __half*)(smem + offAh) + row0 * SA;
    const __half* Al = (const __half*)(smem + offAl) + row0 * SA;
    const __half* W = (const __half*)(smem + offW) + colbase;
    for (int n = 0; n < nt; n++) wmma::fill_fragment(acc[n], 0.0f);
    for (int k = 0; k < K; k += 16) {
        FragA ah, al;
        wmma::load_matrix_sync(ah, Ah + k, SA);
        wmma::load_matrix_sync(al, Al + k, SA);
        for (int n = 0; n < nt; n++) {
            FragB bh;
            wmma::load_matrix_sync(bh, W + k * SW + n * 16, SW);
            wmma::mma_sync(acc[n], ah, bh, acc[n]);
            wmma::mma_sync(acc[n], al, bh, acc[n]);
        }
    }
}

__device__ __forceinline__ void load_W_seg(char* smem, int goff, int K, int N, int SW,
                                           int off, int tid, int nthr) {
    const u32* gw = (const u32*)(g_W + goff);
    int total2 = K * N / 2;
    for (int i2 = tid; i2 < total2; i2 += nthr) {
        int k = (2 * i2) / N, n = (2 * i2) % N;
        *(u32*)(smem + off + (k * SW + n) * 2) = gw[i2];
    }
}

__device__ __forceinline__ void store_A8(char* smem, int offAh, int offAl, int row,
                                         int col, const float* v) {
#pragma unroll
    for (int j = 0; j < 8; j += 2) {
        u32 hi, lo;
        split2(v[j], v[j + 1], hi, lo);
        int d = (row * SA + col + j) * 2;
        *(u32*)(smem + offAh + d) = hi;
        *(u32*)(smem + offAl + d) = lo;
    }
}

// ---------------------------------------------------------------------------
__global__ void zero_kernel(int nNodes) {
    int total = nNodes * 64 + nNodes + 128;
    for (int i = blockIdx.x * blockDim.x + threadIdx.x; i < total;
         i += gridDim.x * blockDim.x) {
        if (i < nNodes * 64) g_ve[i] = 0.0f;
        else if (i < nNodes * 64 + nNodes) g_cnt[i - nNodes * 64] = 0.0f;
        else {
            int j = i - nNodes * 64 - nNodes;
            if (j < 64) g_ue[j] = 0.0f; else g_uv[j - 64] = 0.0f;
        }
    }
}

__global__ void pre_attr_kernel(const float* __restrict__ ga,
                                const float* __restrict__ w,
                                const float* __restrict__ b) {
    __shared__ float sg[64];
    int t = threadIdx.x;
    sg[t] = ga[t];
    __syncthreads();
    float acc = b[t];
    for (int k = 0; k < 64; k++) acc = fmaf(sg[k], w[k * 64 + t], acc);
    g_u_pre[t] = sp(acc);
}

__global__ void const_kernel(const float* __restrict__ ew0,
                             const float* __restrict__ eb0,
                             const float* __restrict__ nw0,
                             const float* __restrict__ nb0) {
    __shared__ float su[64];
    int t = threadIdx.x;  // 128
    if (t < 64) su[t] = g_u_pre[t];
    __syncthreads();
    float a = eb0[t], c = nb0[t];
    for (int k = 0; k < 64; k++) {
        a = fmaf(su[k], ew0[(192 + k) * 128 + t], a);
        c = fmaf(su[k], nw0[(128 + k) * 128 + t], c);
    }
    g_ce[t] = a;
    g_cn[t] = c;
}

__global__ void prep_w_kernel(const float* pw, const float* ew0,
                              const float* ew1, const float* ew2,
                              const float* nw0, const float* nw1,
                              const float* nw2) {
    const float* srcs[7] = {pw, ew0 + 128 * 128, ew1, ew2, nw0, nw1, nw2};
    const int KN[7] = {4096, 8192, 16384, 8192, 16384, 16384, 8192};
    const int off[7] = {0, 4096, 12288, 28672, 36864, 53248, 69632};
#pragma unroll 1
    for (int s = 0; s < 7; s++) {
        const float* sc = srcs[s];
        for (int i = blockIdx.x * blockDim.x + threadIdx.x; i < KN[s];
             i += gridDim.x * blockDim.x)
            g_W[off[s] + i] = __float2half_rn(sc[i]);
    }
}

// ---------------------------------------------------------------------------
__global__ __launch_bounds__(128) void pre_nodeA_kernel(
    const float* __restrict__ nf, const float* __restrict__ pw,
    const float* __restrict__ pb, const float* __restrict__ ew0) {
    __shared__ float snf[2048];
    __shared__ float sv[2048];
    int tid = threadIdx.x;
    size_t base = (size_t)blockIdx.x * 32;

    for (int i = tid; i < 512; i += 128)
        ((float4*)snf)[i] = ((const float4*)(nf + base * 64))[i];
    __syncthreads();

    {
        int col = tid & 63, hf = tid >> 6;
        float bb = pb[col];
        float acc[16];
#pragma unroll
        for (int i = 0; i < 16; i++) acc[i] = bb;
        const float* xr = snf + hf * 16 * 64;
        for (int k = 0; k < 64; k += 4) {
            float wa = __ldg(pw + k * 64 + col), wb = __ldg(pw + (k + 1) * 64 + col);
            float wc = __ldg(pw + (k + 2) * 64 + col), wd = __ldg(pw + (k + 3) * 64 + col);
#pragma unroll
            for (int i = 0; i < 16; i++) {
                float4 xv = *(const float4*)(xr + i * 64 + k);
                acc[i] = fmaf(xv.x, wa, acc[i]);
                acc[i] = fmaf(xv.y, wb, acc[i]);
                acc[i] = fmaf(xv.z, wc, acc[i]);
                acc[i] = fmaf(xv.w, wd, acc[i]);
            }
        }
#pragma unroll
        for (int i = 0; i < 16; i++) {
            float v = sp(acc[i]);
            sv[(hf * 16 + i) * 64 + col] = v;
            g_v_pre[(base + hf * 16 + i) * 64 + col] = v;
        }
    }
    __syncthreads();

    float* Asf = (float*)g_As;
    float* Adf = (float*)g_Ad;
    int j = tid;
#pragma unroll 1
    for (int m = 0; m < 2; m++) {
        const float* w = ew0 + (size_t)m * 64 * 128;
        float acc[32];
#pragma unroll
        for (int e = 0; e < 32; e++) acc[e] = 0.0f;
        for (int k = 0; k < 64; k += 4) {
            float wa = __ldg(w + k * 128 + j), wb = __ldg(w + (k + 1) * 128 + j);
            float wc = __ldg(w + (k + 2) * 128 + j), wd = __ldg(w + (k + 3) * 128 + j);
#pragma unroll
            for (int e = 0; e < 32; e++) {
                float4 xv = *(const float4*)(sv + e * 64 + k);
                acc[e] = fmaf(xv.x, wa, acc[e]);
                acc[e] = fmaf(xv.y, wb, acc[e]);
                acc[e] = fmaf(xv.z, wc, acc[e]);
                acc[e] = fmaf(xv.w, wd, acc[e]);
            }
        }
        float* dstp = m ? Adf : Asf;
#pragma unroll
        for (int e = 0; e < 32; e++) dstp[(base + e) * 128 + j] = acc[e];
    }
}

// ---------------------------------------------------------------------------
// persistent edge kernel: 128 edges / iteration, 512 threads / 16 warps
// warp = (slab 0..7, h 0..1): rows slab*16..+16, cols h*(N/2)..
// ---------------------------------------------------------------------------
__global__ __launch_bounds__(512) void edge_kernel(
    const float* __restrict__ ef, const int* __restrict__ srcI,
    const int* __restrict__ dstI, const float* __restrict__ pb,
    const float* __restrict__ b1, const float* __restrict__ b2,
    float* __restrict__ e_out, int nTiles) {
    extern __shared__ char smem[];
    int tid = threadIdx.x, wid = tid >> 5, lane = tid & 31;

    int*   s_src = (int*)(smem + E_MISC);
    int*   s_dst = (int*)(smem + E_MISC + 512);
    float* s_pb  = (float*)(smem + E_MISC + 1024);
    float* s_b1  = (float*)(smem + E_MISC + 1280);
    float* s_b2  = (float*)(smem + E_MISC + 1792);
    float* s_ce  = (float*)(smem + E_MISC + 2048);
    float* spart = (float*)(smem + E_MISC + 2560);
    float* stg   = (float*)(smem + E_STG) + wid * 320;
    float* fstage = (float*)(smem + E_A_H);  // f32 [128][68]

    load_W_seg(smem, 0,     64, 64,  72, E_WP, tid, 512);
    load_W_seg(smem, 4096,  64, 128, 136, E_W0, tid, 512);
    load_W_seg(smem, 12288, 128, 128, 136, E_W1, tid, 512);
    load_W_seg(smem, 28672, 128, 64,  72, E_W2, tid, 512);
    if (tid < 128) {
        s_ce[tid] = g_ce[tid];
        s_b1[tid] = __ldg(b1 + tid);
    } else if (tid < 192) {
        s_pb[tid - 128] = __ldg(pb + tid - 128);
    } else if (tid < 256) {
        s_b2[tid - 192] = __ldg(b2 + tid - 192);
    }

    int slab = wid & 7, h = wid >> 3, row0 = slab * 16;
    int r = lane >> 1, c0 = (lane & 1) * 8, row = row0 + r;
    float ue_acc = 0.0f;
    FragC acc[4];

    for (int t = blockIdx.x; t < nTiles; t += gridDim.x) {
        size_t base = (size_t)t * 128;
        __syncthreads();

        if (tid < 128) {
            s_src[tid] = srcI[base + tid];
            s_dst[tid] = dstI[base + tid];
        }
        // stage ef -> A hi/lo: 2048 float4s
        for (int i = tid; i < 2048; i += 512) {
            int rr = i >> 4, q = i & 15;
            float4 v = __ldg((const float4*)(ef + (base + rr) * 64) + q);
            int c = q * 4;
            u32 hi, lo;
            split2(v.x, v.y, hi, lo);
            *(u32*)(smem + E_A_H + (rr * SA + c) * 2) = hi;
            *(u32*)(smem + E_A_L + (rr * SA + c) * 2) = lo;
            split2(v.z, v.w, hi, lo);
            *(u32*)(smem + E_A_H + (rr * SA + c + 2) * 2) = hi;
            *(u32*)(smem + E_A_L + (rr * SA + c + 2) * 2) = lo;
        }
        __syncthreads();

        // ---- phase 0: pre-edge K=64 N=64 ----
        mma_half(smem, E_A_H, E_A_L, E_WP, row0, 64, 72, h * 32, 2, acc);
        __syncthreads();
#pragma unroll
        for (int n = 0; n < 2; n++) {
            wmma::store_matrix_sync(stg, acc[n], 20, wmma::mem_row_major);
            __syncwarp();
            int col = h * 32 + n * 16 + c0;
            float v[8];
#pragma unroll
            for (int j = 0; j < 8; j++) v[j] = sp(stg[r * 20 + c0 + j] + s_pb[col + j]);
            store_A8(smem, E_A_H, E_A_L, row, col, v);
            __syncwarp();
        }
        __syncthreads();

        // ---- phase 1: L0 K=64 N=128 (+ As[src]+Ad[dst]+ce) ----
        mma_half(smem, E_A_H, E_A_L, E_W0, row0, 64, 136, h * 64, 4, acc);
        __syncthreads();
        {
            const float4* as4 = (const float4*)g_As + (size_t)s_src[row] * 32;
            const float4* ad4 = (const float4*)g_Ad + (size_t)s_dst[row] * 32;
#pragma unroll
            for (int n = 0; n < 4; n++) {
                wmma::store_matrix_sync(stg, acc[n], 20, wmma::mem_row_major);
                __syncwarp();
                int col = h * 64 + n * 16 + c0;
                float4 a0 = __ldg(as4 + (col >> 2)), a1 = __ldg(as4 + (col >> 2) + 1);
                float4 d0 = __ldg(ad4 + (col >> 2)), d1 = __ldg(ad4 + (col >> 2) + 1);
                float ga[8] = {a0.x + d0.x, a0.y + d0.y, a0.z + d0.z, a0.w + d0.w,
                               a1.x + d1.x, a1.y + d1.y, a1.z + d1.z, a1.w + d1.w};
                float v[8];
#pragma unroll
                for (int j = 0; j < 8; j++)
                    v[j] = sp(stg[r * 20 + c0 + j] + ga[j] + s_ce[col + j]);
                store_A8(smem, E_A_H, E_A_L, row, col, v);
                __syncwarp();
            }
        }
        __syncthreads();

        // ---- phase 2: L1 K=128 N=128 ----
        mma_half(smem, E_A_H, E_A_L, E_W1, row0, 128, 136, h * 64, 4, acc);
        __syncthreads();
#pragma unroll
        for (int n = 0; n < 4; n++) {
            wmma::store_matrix_sync(stg, acc[n], 20, wmma::mem_row_major);
            __syncwarp();
            int col = h * 64 + n * 16 + c0;
            float v[8];
#pragma unroll
            for (int j = 0; j < 8; j++) v[j] = sp(stg[r * 20 + c0 + j] + s_b1[col + j]);
            store_A8(smem, E_A_H, E_A_L, row, col, v);
            __syncwarp();
        }
        __syncthreads();

        // ---- phase 3: L2 K=128 N=64 ----
        mma_half(smem, E_A_H, E_A_L, E_W2, row0, 128, 72, h * 32, 2, acc);
        __syncthreads();
        {
            int dnode = s_dst[row];
#pragma unroll
            for (int n = 0; n < 2; n++) {
                wmma::store_matrix_sync(stg, acc[n], 20, wmma::mem_row_major);
                __syncwarp();
                int col = h * 32 + n * 16 + c0;
                float v[8];
#pragma unroll
                for (int j = 0; j < 8; j++)
                    v[j] = sp(stg[r * 20 + c0 + j] + s_b2[col + j]);
                size_t gidx = (base + row) * 64 + col;
                float4 e0 = __ldg((const float4*)(ef + gidx));
                float4 e1 = __ldg((const float4*)(ef + gidx) + 1);
                float4 o0 = {v[0] + e0.x, v[1] + e0.y, v[2] + e0.z, v[3] + e0.w};
                float4 o1 = {v[4] + e1.x, v[5] + e1.y, v[6] + e1.z, v[7] + e1.w};
                *(float4*)(e_out + gidx) = o0;
                *((float4*)(e_out + gidx) + 1) = o1;
                float* vrow = &g_ve[(size_t)dnode * 64 + col];
#pragma unroll
                for (int j = 0; j < 8; j++) {
                    atomicAdd(vrow + j, v[j]);
                    fstage[row * 68 + col + j] = v[j];
                }
                if (n == 0 && h == 0 && (lane & 1) == 0)
                    atomicAdd(&g_cnt[dnode], 1.0f);
                __syncwarp();
            }
        }
        __syncthreads();

        // ue partial: 512 threads, 16 rows each
        {
            int col = tid & 63, q = tid >> 6;
            float s = 0.0f;
#pragma unroll
            for (int rr = q * 16; rr < q * 16 + 16; rr++) s += fstage[rr * 68 + col];
            spart[tid] = s;
        }
        __syncthreads();
        if (tid < 64) {
            float s = 0.0f;
#pragma unroll
            for (int q = 0; q < 8; q++) s += spart[q * 64 + tid];
            ue_acc += s;
        }
    }
    if (tid < 64) atomicAdd(&g_ue[tid], ue_acc);
}

// ---------------------------------------------------------------------------
// persistent node kernel: 128 nodes / iteration, 512 threads
// ---------------------------------------------------------------------------
__global__ __launch_bounds__(512) void node_kernel(
    const float* __restrict__ nf, const float* __restrict__ b1,
    const float* __restrict__ b2, float* __restrict__ v_out, int nNodes,
    int nTiles) {
    extern __shared__ char smem[];
    int tid = threadIdx.x, wid = tid >> 5, lane = tid & 31;

    float* s_cn  = (float*)(smem + N_MISC);
    float* s_b1  = (float*)(smem + N_MISC + 512);
    float* s_b2  = (float*)(smem + N_MISC + 1024);
    float* spart = (float*)(smem + N_MISC + 1280);
    float* stg   = (float*)(smem + N_STG) + wid * 320;
    float* fstage = (float*)(smem + N_A_H);

    load_W_seg(smem, 36864, 128, 128, 136, N_W0, tid, 512);
    load_W_seg(smem, 53248, 128, 128, 136, N_W1, tid, 512);
    load_W_seg(smem, 69632, 128, 64,  72, N_W2, tid, 512);
    if (tid < 128) {
        s_cn[tid] = g_cn[tid];
        s_b1[tid] = __ldg(b1 + tid);
    } else if (tid < 192) {
        s_b2[tid - 128] = (tid - 128 < 64) ? __ldg(b2 + tid - 128) : 0.0f;
    }

    int slab = wid & 7, h = wid >> 3, row0 = slab * 16;
    int r = lane >> 1, c0 = (lane & 1) * 8, row = row0 + r;
    float uv_acc = 0.0f;
    FragC acc[4];

    for (int t = blockIdx.x; t < nTiles; t += gridDim.x) {
        size_t base = (size_t)t * 128;
        __syncthreads();

        // stage X = [v_pre | ve_mean] (K=128): rows 128, each thread 32 cols
        {
            int rr = tid & 127, hh = tid >> 7;  // hh 0..3
            size_t gn = base + rr;
            if (gn >= (size_t)nNodes) gn = nNodes - 1;
            const float4* g4;
            float scale = 1.0f;
            if (hh < 2) {
                g4 = (const float4*)(g_v_pre + gn * 64) + hh * 8;
            } else {
                g4 = (const float4*)(g_ve + gn * 64) + (hh - 2) * 8;
                scale = 1.0f / fmaxf(g_cnt[gn], 1.0f);
            }
#pragma unroll
            for (int q = 0; q < 8; q++) {
                float4 v = __ldg(g4 + q);
                v.x *= scale; v.y *= scale; v.z *= scale; v.w *= scale;
                int c = hh * 32 + q * 4;
                u32 hi, lo;
                split2(v.x, v.y, hi, lo);
                *(u32*)(smem + N_A_H + (rr * SA + c) * 2) = hi;
                *(u32*)(smem + N_A_L + (rr * SA + c) * 2) = lo;
                split2(v.z, v.w, hi, lo);
                *(u32*)(smem + N_A_H + (rr * SA + c + 2) * 2) = hi;
                *(u32*)(smem + N_A_L + (rr * SA + c + 2) * 2) = lo;
            }
        }
        __syncthreads();

        bool valid = (base + row) < (size_t)nNodes;

        // ---- L0: K=128 N=128 ----
        mma_half(smem, N_A_H, N_A_L, N_W0, row0, 128, 136, h * 64, 4, acc);
        __syncthreads();
#pragma unroll
        for (int n = 0; n < 4; n++) {
            wmma::store_matrix_sync(stg, acc[n], 20, wmma::mem_row_major);
            __syncwarp();
            int col = h * 64 + n * 16 + c0;
            float v[8];
#pragma unroll
            for (int j = 0; j < 8; j++) v[j] = sp(stg[r * 20 + c0 + j] + s_cn[col + j]);
            store_A8(smem, N_A_H, N_A_L, row, col, v);
            __syncwarp();
        }
        __syncthreads();

        // ---- L1: K=128 N=128 ----
        mma_half(smem, N_A_H, N_A_L, N_W1, row0, 128, 136, h * 64, 4, acc);
        __syncthreads();
#pragma unroll
        for (int n = 0; n < 4; n++) {
            wmma::store_matrix_sync(stg, acc[n], 20, wmma::mem_row_major);
            __syncwarp();
            int col = h * 64 + n * 16 + c0;
            float v[8];
#pragma unroll
            for (int j = 0; j < 8; j++) v[j] = sp(stg[r * 20 + c0 + j] + s_b1[col + j]);
            store_A8(smem, N_A_H, N_A_L, row, col, v);
            __syncwarp();
        }
        __syncthreads();

        // ---- L2: K=128 N=64 ----
        mma_half(smem, N_A_H, N_A_L, N_W2, row0, 128, 72, h * 32, 2, acc);
        __syncthreads();
#pragma unroll
        for (int n = 0; n < 2; n++) {
            wmma::store_matrix_sync(stg, acc[n], 20, wmma::mem_row_major);
            __syncwarp();
            int col = h * 32 + n * 16 + c0;
            float v[8];
#pragma unroll
            for (int j = 0; j < 8; j++) v[j] = sp(stg[r * 20 + c0 + j] + s_b2[col + j]);
            if (valid) {
                size_t gidx = (base + row) * 64 + col;
                float4 e0 = __ldg((const float4*)(nf + gidx));
                float4 e1 = __ldg((const float4*)(nf + gidx) + 1);
                float4 o0 = {v[0] + e0.x, v[1] + e0.y, v[2] + e0.z, v[3] + e0.w};
                float4 o1 = {v[4] + e1.x, v[5] + e1.y, v[6] + e1.z, v[7] + e1.w};
                *(float4*)(v_out + gidx) = o0;
                *((float4*)(v_out + gidx) + 1) = o1;
            }
#pragma unroll
            for (int j = 0; j < 8; j++)
                fstage[row * 68 + col + j] = valid ? v[j] : 0.0f;
            __syncwarp();
        }
        __syncthreads();

        {
            int col = tid & 63, q = tid >> 6;
            float s = 0.0f;
#pragma unroll
            for (int rr = q * 16; rr < q * 16 + 16; rr++) s += fstage[rr * 68 + col];
            spart[tid] = s;
        }
        __syncthreads();
        if (tid < 64) {
            float s = 0.0f;
#pragma unroll
            for (int q = 0; q < 8; q++) s += spart[q * 64 + tid];
            uv_acc += s;
        }
    }
    if (tid < 64) atomicAdd(&g_uv[tid], uv_acc);
}

// ---------------------------------------------------------------------------
__global__ void attr_kernel(const float* __restrict__ ga,
                            const float* __restrict__ w0,
                            const float* __restrict__ b0,
                            const float* __restrict__ w1,
                            const float* __restrict__ b1,
                            const float* __restrict__ w2,
                            const float* __restrict__ b2,
                            float* __restrict__ out, float invE, float invN) {
    __shared__ float x[192], h0[128], h1[128];
    int t = threadIdx.x;
    if (t < 64) {
        x[t]       = g_u_pre[t];
        x[64 + t]  = g_ue[t] * invE;
        x[128 + t] = g_uv[t] * invN;
    }
    __syncthreads();
    float acc = b0[t];
    for (int k = 0; k < 192; k++) acc = fmaf(x[k], w0[k * 128 + t], acc);
    h0[t] = sp(acc);
    __syncthreads();
    acc = b1[t];
    for (int k = 0; k < 128; k++) acc = fmaf(h0[k], w1[k * 128 + t], acc);
    h1[t] = sp(acc);
    __syncthreads();
    if (t < 64) {
        float a = b2[t];
        for (int k = 0; k < 128; k++) a = fmaf(h1[k], w2[k * 64 + t], a);
        out[t] = sp(a) + ga[t];
    }
}

// ---------------------------------------------------------------------------
extern "C" void kernel_launch(void* const* d_in, const int* in_sizes, int n_in,
                              void* d_out, int out_size) {
    const float* edge_feat  = (const float*)d_in[0];
    const float* node_feat  = (const float*)d_in[1];
    const float* graph_attr = (const float*)d_in[2];
    const int*   src        = (const int*)d_in[3];
    const int*   dst        = (const int*)d_in[4];
    const float* pre_edge_w = (const float*)d_in[5];
    const float* pre_edge_b = (const float*)d_in[6];
    const float* pre_node_w = (const float*)d_in[7];
    const float* pre_node_b = (const float*)d_in[8];
    const float* pre_attr_w = (const float*)d_in[9];
    const float* pre_attr_b = (const float*)d_in[10];
    const float* edge_w0 = (const float*)d_in[11];
    const float* edge_b0 = (const float*)d_in[12];
    const float* edge_w1 = (const float*)d_in[13];
    const float* edge_b1 = (const float*)d_in[14];
    const float* edge_w2 = (const float*)d_in[15];
    const float* edge_b2 = (const float*)d_in[16];
    const float* node_w0 = (const float*)d_in[17];
    const float* node_b0 = (const float*)d_in[18];
    const float* node_w1 = (const float*)d_in[19];
    const float* node_b1 = (const float*)d_in[20];
    const float* node_w2 = (const float*)d_in[21];
    const float* node_b2 = (const float*)d_in[22];
    const float* attr_w0 = (const float*)d_in[23];
    const float* attr_b0 = (const float*)d_in[24];
    const float* attr_w1 = (const float*)d_in[25];
    const float* attr_b1 = (const float*)d_in[26];
    const float* attr_w2 = (const float*)d_in[27];
    const float* attr_b2 = (const float*)d_in[28];

    float* out = (float*)d_out;
    int E = in_sizes[3];
    int N = in_sizes[1] / 64;
    int eTiles = E / 128;
    int nTiles = (N + 127) / 128;

    cudaFuncSetAttribute(edge_kernel, cudaFuncAttributeMaxDynamicSharedMemorySize,
                         E_TOTAL);
    cudaFuncSetAttribute(node_kernel, cudaFuncAttributeMaxDynamicSharedMemorySize,
                         N_TOTAL);

    zero_kernel<<<256, 256>>>(N);
    pre_attr_kernel<<<1, 64>>>(graph_attr, pre_attr_w, pre_attr_b);
    const_kernel<<<1, 128>>>(edge_w0, edge_b0, node_w0, node_b0);
    prep_w_kernel<<<64, 256>>>(pre_edge_w, edge_w0, edge_w1, edge_w2, node_w0,
                               node_w1, node_w2);
    pre_nodeA_kernel<<<N / 32, 128>>>(node_feat, pre_node_w, pre_node_b, edge_w0);
    edge_kernel<<<NUM_CTAS, 512, E_TOTAL>>>(edge_feat, src, dst, pre_edge_b,
                                            edge_b1, edge_b2, out, eTiles);
    node_kernel<<<NUM_CTAS, 512, N_TOTAL>>>(node_feat, node_b1, node_b2,
                                            out + (size_t)E * 64, N, nTiles);
    attr_kernel<<<1, 128>>>(graph_attr, attr_w0, attr_b0, attr_w1, attr_b1,
                            attr_w2, attr_b2,
                            out + (size_t)E * 64 + (size_t)N * 64,
                            1.0f / (float)E, 1.0f / (float)N);
}